// round 3
// baseline (speedup 1.0000x reference)
#include <cuda_runtime.h>
#include <cstdint>

// ---------------------------------------------------------------------------
// MACE invariant message passing, fused:
//   h = node_feats @ W_up
//   m[e,lm,c] = h[sender[e],c] * edge_attrs[e,lm] * edge_feats[e,l_of_lm[lm],c]
//   msg[n]    = segment_sum over receiver
//   out[n,lm] = msg[n,lm] @ ( W_lin[l] @ W_skip[elem[n],l] / 16 )
// ---------------------------------------------------------------------------

#define N_MAX 6144
#define E_MAX 131072
#define NE_MAX 16

// Static device scratch (allocation-free per harness rules)
__device__ float d_h[(size_t)N_MAX * 128];
__device__ float d_msg[(size_t)N_MAX * 16 * 128];
__device__ float d_Wc[(size_t)NE_MAX * 4 * 128 * 128];
__device__ int   d_sorted[E_MAX];
__device__ int   d_counts[N_MAX];
__device__ int   d_offsets[N_MAX + 1];
__device__ int   d_cursor[N_MAX];
__device__ int   d_node_by_elem[N_MAX];
__device__ int   d_elem_off[NE_MAX + 1];
__device__ int   d_elem_cur[NE_MAX];

// ---------------------------------------------------------------------------
// Counting sort of edges by receiver
// ---------------------------------------------------------------------------
__global__ void zero_counts_kernel(int n) {
    int i = blockIdx.x * blockDim.x + threadIdx.x;
    if (i < n) d_counts[i] = 0;
}

__global__ void hist_kernel(const int* __restrict__ recv, int E) {
    int i = blockIdx.x * blockDim.x + threadIdx.x;
    if (i < E) atomicAdd(&d_counts[recv[i]], 1);
}

__global__ void scan_kernel(int N) {
    __shared__ int sh[1024];
    __shared__ int s_carry;
    int tid = threadIdx.x;
    if (tid == 0) { s_carry = 0; d_offsets[0] = 0; }
    __syncthreads();
    for (int base = 0; base < N; base += 1024) {
        int v = (base + tid < N) ? d_counts[base + tid] : 0;
        sh[tid] = v;
        __syncthreads();
        #pragma unroll
        for (int o = 1; o < 1024; o <<= 1) {
            int t = (tid >= o) ? sh[tid - o] : 0;
            __syncthreads();
            sh[tid] += t;
            __syncthreads();
        }
        int inc = sh[tid] + s_carry;
        if (base + tid < N) {
            d_offsets[base + tid + 1] = inc;
            d_cursor[base + tid] = inc - v;   // exclusive offset = segment start
        }
        int total = sh[1023];
        __syncthreads();
        if (tid == 0) s_carry += total;
        __syncthreads();
    }
}

__global__ void scatter_kernel(const int* __restrict__ recv, int E) {
    int i = blockIdx.x * blockDim.x + threadIdx.x;
    if (i < E) {
        int pos = atomicAdd(&d_cursor[recv[i]], 1);
        d_sorted[pos] = i;
    }
}

// ---------------------------------------------------------------------------
// Group nodes by element (single block)
// ---------------------------------------------------------------------------
__global__ void elem_group_kernel(const int* __restrict__ node_elem, int N, int NE) {
    __shared__ int scnt[NE_MAX];
    int tid = threadIdx.x;
    if (tid < NE) scnt[tid] = 0;
    __syncthreads();
    for (int i = tid; i < N; i += blockDim.x) atomicAdd(&scnt[node_elem[i]], 1);
    __syncthreads();
    if (tid == 0) {
        int run = 0;
        for (int e = 0; e < NE; e++) { d_elem_off[e] = run; d_elem_cur[e] = run; run += scnt[e]; }
        d_elem_off[NE] = run;
    }
    __syncthreads();
    for (int i = tid; i < N; i += blockDim.x) {
        int pos = atomicAdd(&d_elem_cur[node_elem[i]], 1);
        d_node_by_elem[pos] = i;
    }
}

// ---------------------------------------------------------------------------
// Edge accumulation: one CTA per node, 256 threads.
// thread t: channel c = t & 127, half = t >> 7 (half 0 -> lm 0..7, half 1 -> lm 8..15)
// l_of_lm: [0,1,1,1, 2,2,2,2, 2,3,3,3, 3,3,3,3]
// ---------------------------------------------------------------------------
__global__ __launch_bounds__(256) void edge_accum_kernel(
    const float* __restrict__ edge_attrs,   // [E,16]
    const float* __restrict__ edge_feats,   // [E,4,128]
    const int*   __restrict__ sender,       // [E]
    int N)
{
    int n = blockIdx.x;
    int tid = threadIdx.x;
    int c = tid & 127;
    int half = tid >> 7;

    __shared__ float s_attr[16][16];
    __shared__ int   s_e[16];
    __shared__ int   s_send[16];

    float acc[8] = {0.f, 0.f, 0.f, 0.f, 0.f, 0.f, 0.f, 0.f};

    int beg = d_offsets[n];
    int end = d_offsets[n + 1];

    for (int base = beg; base < end; base += 16) {
        int m = end - base;
        if (m > 16) m = 16;
        if (tid < m) {
            int ee = d_sorted[base + tid];
            s_e[tid] = ee;
            s_send[tid] = sender[ee];
        }
        for (int i = tid; i < m * 16; i += 256) {
            int j = i >> 4;
            int ee2 = d_sorted[base + j];
            s_attr[j][i & 15] = edge_attrs[(size_t)ee2 * 16 + (i & 15)];
        }
        __syncthreads();

        for (int j = 0; j < m; j++) {
            const float* efp = edge_feats + (size_t)s_e[j] * 512;
            float hs = d_h[(size_t)s_send[j] * 128 + c];
            if (half == 0) {
                float e0 = efp[c], e1 = efp[128 + c], e2 = efp[256 + c];
                float p0 = hs * e0, p1 = hs * e1, p2 = hs * e2;
                acc[0] += p0 * s_attr[j][0];
                acc[1] += p1 * s_attr[j][1];
                acc[2] += p1 * s_attr[j][2];
                acc[3] += p1 * s_attr[j][3];
                acc[4] += p2 * s_attr[j][4];
                acc[5] += p2 * s_attr[j][5];
                acc[6] += p2 * s_attr[j][6];
                acc[7] += p2 * s_attr[j][7];
            } else {
                float e2 = efp[256 + c], e3 = efp[384 + c];
                float p2 = hs * e2, p3 = hs * e3;
                acc[0] += p2 * s_attr[j][8];
                acc[1] += p3 * s_attr[j][9];
                acc[2] += p3 * s_attr[j][10];
                acc[3] += p3 * s_attr[j][11];
                acc[4] += p3 * s_attr[j][12];
                acc[5] += p3 * s_attr[j][13];
                acc[6] += p3 * s_attr[j][14];
                acc[7] += p3 * s_attr[j][15];
            }
        }
        __syncthreads();
    }

    size_t ob = ((size_t)n * 16 + half * 8) * 128 + c;
    #pragma unroll
    for (int j = 0; j < 8; j++) d_msg[ob + (size_t)j * 128] = acc[j];
}

// ---------------------------------------------------------------------------
// Register-tiled fp32 SGEMM, K=128, BN=128 fixed. BM=64, BK=16, 256 threads,
// thread tile 8x4. DST=0 writes d_h, DST=1 writes d_Wc.
// A offset = y*sAy + z*sAz, likewise B, C.
// ---------------------------------------------------------------------------
template <int DST>
__global__ __launch_bounds__(256) void sgemm128_kernel(
    const float* __restrict__ A, const float* __restrict__ B,
    int M, float scale,
    long sAy, long sBy, long sCy,
    long sAz, long sBz, long sCz)
{
    float* Cbase = (DST == 0) ? d_h : d_Wc;
    A += (long)blockIdx.y * sAy + (long)blockIdx.z * sAz;
    B += (long)blockIdx.y * sBy + (long)blockIdx.z * sBz;
    float* C = Cbase + (long)blockIdx.y * sCy + (long)blockIdx.z * sCz;

    __shared__ float As[16 * 72];   // row stride 72 floats: 16B aligned rows, low conflicts
    __shared__ float Bs[16 * 128];

    int tid = threadIdx.x;
    int ty = tid >> 5;      // 0..7  -> row group of 8
    int tx = tid & 31;      // 0..31 -> col group of 4
    int row0 = blockIdx.x * 64;

    float acc[8][4];
    #pragma unroll
    for (int i = 0; i < 8; i++)
        #pragma unroll
        for (int j = 0; j < 4; j++) acc[i][j] = 0.f;

    for (int kc = 0; kc < 128; kc += 16) {
        #pragma unroll
        for (int i = 0; i < 4; i++) {
            int idx = tid + i * 256;
            int r = idx >> 4, kk = idx & 15;
            int row = row0 + r;
            As[kk * 72 + r] = (row < M) ? A[(size_t)row * 128 + kc + kk] : 0.f;
        }
        #pragma unroll
        for (int i = 0; i < 8; i++) {
            int idx = tid + i * 256;
            int kk = idx >> 7, d = idx & 127;
            Bs[kk * 128 + d] = B[(size_t)(kc + kk) * 128 + d];
        }
        __syncthreads();
        #pragma unroll
        for (int kk = 0; kk < 16; kk++) {
            float4 a0 = *(const float4*)&As[kk * 72 + ty * 8];
            float4 a1 = *(const float4*)&As[kk * 72 + ty * 8 + 4];
            float4 b  = *(const float4*)&Bs[kk * 128 + tx * 4];
            float av[8] = {a0.x, a0.y, a0.z, a0.w, a1.x, a1.y, a1.z, a1.w};
            float bv[4] = {b.x, b.y, b.z, b.w};
            #pragma unroll
            for (int i = 0; i < 8; i++)
                #pragma unroll
                for (int j = 0; j < 4; j++) acc[i][j] += av[i] * bv[j];
        }
        __syncthreads();
    }

    #pragma unroll
    for (int i = 0; i < 8; i++) {
        int row = row0 + ty * 8 + i;
        if (row < M) {
            float4 v = make_float4(acc[i][0] * scale, acc[i][1] * scale,
                                   acc[i][2] * scale, acc[i][3] * scale);
            *(float4*)&C[(size_t)row * 128 + tx * 4] = v;
        }
    }
}

// ---------------------------------------------------------------------------
// Grouped output GEMM: for group (element e, angular l), rows = cnt(e)*(2l+1),
// each row is msg[(node*16+lm)*128 .. +128), B = Wc[e][l] (128x128).
// Same 64x128x128 tiling; rows gathered through s_off.
// ---------------------------------------------------------------------------
__global__ __launch_bounds__(256) void out_gemm_kernel(float* __restrict__ out)
{
    int l = blockIdx.y & 3;
    int e = blockIdx.y >> 2;
    int tw = 2 * l + 1;
    int cbeg = d_elem_off[e];
    int rows = (d_elem_off[e + 1] - cbeg) * tw;
    const float* B = d_Wc + (size_t)(e * 4 + l) * 16384;

    __shared__ float As[16 * 72];
    __shared__ float Bs[16 * 128];
    __shared__ long  s_off[64];

    int tid = threadIdx.x;
    int ty = tid >> 5;
    int tx = tid & 31;

    for (int tile = blockIdx.x * 64; tile < rows; tile += gridDim.x * 64) {
        if (tid < 64) {
            int r = tile + tid;
            long off = -1;
            if (r < rows) {
                int node = d_node_by_elem[cbeg + r / tw];
                int lm = l * l + (r % tw);
                off = ((long)node * 16 + lm) * 128;
            }
            s_off[tid] = off;
        }
        __syncthreads();

        float acc[8][4];
        #pragma unroll
        for (int i = 0; i < 8; i++)
            #pragma unroll
            for (int j = 0; j < 4; j++) acc[i][j] = 0.f;

        for (int kc = 0; kc < 128; kc += 16) {
            #pragma unroll
            for (int i = 0; i < 4; i++) {
                int idx = tid + i * 256;
                int r = idx >> 4, kk = idx & 15;
                long off = s_off[r];
                As[kk * 72 + r] = (off >= 0) ? d_msg[off + kc + kk] : 0.f;
            }
            #pragma unroll
            for (int i = 0; i < 8; i++) {
                int idx = tid + i * 256;
                int kk = idx >> 7, d = idx & 127;
                Bs[kk * 128 + d] = B[(size_t)(kc + kk) * 128 + d];
            }
            __syncthreads();
            #pragma unroll
            for (int kk = 0; kk < 16; kk++) {
                float4 a0 = *(const float4*)&As[kk * 72 + ty * 8];
                float4 a1 = *(const float4*)&As[kk * 72 + ty * 8 + 4];
                float4 b  = *(const float4*)&Bs[kk * 128 + tx * 4];
                float av[8] = {a0.x, a0.y, a0.z, a0.w, a1.x, a1.y, a1.z, a1.w};
                float bv[4] = {b.x, b.y, b.z, b.w};
                #pragma unroll
                for (int i = 0; i < 8; i++)
                    #pragma unroll
                    for (int j = 0; j < 4; j++) acc[i][j] += av[i] * bv[j];
            }
            __syncthreads();
        }

        #pragma unroll
        for (int i = 0; i < 8; i++) {
            long off = s_off[ty * 8 + i];
            if (off >= 0) {
                float4 v = make_float4(acc[i][0], acc[i][1], acc[i][2], acc[i][3]);
                *(float4*)&out[off + tx * 4] = v;
            }
        }
        __syncthreads();   // protect s_off before next tile
    }
}

// ---------------------------------------------------------------------------
// Launch
// ---------------------------------------------------------------------------
extern "C" void kernel_launch(void* const* d_in, const int* in_sizes, int n_in,
                              void* d_out, int out_size)
{
    const float* node_feats = (const float*)d_in[0];   // [N,128]
    const float* edge_attrs = (const float*)d_in[1];   // [E,16]
    const float* edge_feats = (const float*)d_in[2];   // [E,512]
    const float* W_up       = (const float*)d_in[3];   // [128,128]
    const float* W_lin      = (const float*)d_in[4];   // [4,128,128]
    const float* W_skip     = (const float*)d_in[5];   // [NE,4,128,128]
    const int*   edge_index = (const int*)d_in[6];     // [2,E]
    const int*   node_elem  = (const int*)d_in[7];     // [N]

    int N  = in_sizes[7];
    int E  = in_sizes[1] / 16;
    int NE = in_sizes[5] / (4 * 128 * 128);

    const int* sender = edge_index;
    const int* recv   = edge_index + E;

    // 1. h = node_feats @ W_up
    sgemm128_kernel<0><<<dim3((N + 63) / 64, 1, 1), 256>>>(
        node_feats, W_up, N, 1.0f, 0, 0, 0, 0, 0, 0);

    // 2. counting-sort edges by receiver
    zero_counts_kernel<<<(N + 255) / 256, 256>>>(N);
    hist_kernel<<<(E + 255) / 256, 256>>>(recv, E);
    scan_kernel<<<1, 1024>>>(N);
    scatter_kernel<<<(E + 255) / 256, 256>>>(recv, E);

    // 3. node-by-element grouping
    elem_group_kernel<<<1, 1024>>>(node_elem, N, NE);

    // 4. per-node edge accumulation -> msg
    edge_accum_kernel<<<N, 256>>>(edge_attrs, edge_feats, sender, N);

    // 5. Wc[e,l] = W_lin[l] @ W_skip[e,l] / 16
    sgemm128_kernel<1><<<dim3(2, 4, NE), 256>>>(
        W_lin, W_skip, 128, 1.0f / 16.0f,
        /*sAy*/ 16384, /*sBy*/ 16384, /*sCy*/ 16384,
        /*sAz*/ 0,     /*sBz*/ 65536, /*sCz*/ 65536);

    // 6. grouped output GEMM: out = msg @ Wc[elem, l]
    out_gemm_kernel<<<dim3(64, NE * 4), 256>>>((float*)d_out);
}

// round 4
// speedup vs baseline: 1.1408x; 1.1408x over previous
#include <cuda_runtime.h>
#include <cstdint>

// ---------------------------------------------------------------------------
// MACE invariant message passing, fused:
//   h   = node_feats @ W_up
//   m   = h[sender] * edge_attrs * edge_feats[l_of_lm]   (per edge)
//   msg = segment_sum over receiver
//   out = msg @ ( W_lin[l] @ W_skip[elem,l] / 16 )       (grouped by element)
// ---------------------------------------------------------------------------

typedef unsigned long long u64;

#define N_MAX 6144
#define E_MAX 131072
#define NE_MAX 16
#define AST 132   // As row stride (floats), multiple of 4

// Static device scratch (allocation-free per harness rules)
__device__ float d_h[(size_t)N_MAX * 128];
__device__ float d_msg[(size_t)N_MAX * 16 * 128];
__device__ float d_Wc[(size_t)NE_MAX * 4 * 128 * 128];
__device__ int   d_sorted[E_MAX];
__device__ int   d_counts[N_MAX];
__device__ int   d_offsets[N_MAX + 1];
__device__ int   d_cursor[N_MAX];
__device__ int   d_node_by_elem[N_MAX];
__device__ int   d_elem_off[NE_MAX + 1];
__device__ int   d_elem_cur[NE_MAX];

// --------------------------- f32x2 helpers ---------------------------------
__device__ __forceinline__ u64 pk2(float x) {
    u64 r; asm("mov.b64 %0, {%1, %1};" : "=l"(r) : "f"(x)); return r;
}
__device__ __forceinline__ void fma2(u64& d, u64 a, u64 b) {
    asm("fma.rn.f32x2 %0, %1, %2, %0;" : "+l"(d) : "l"(a), "l"(b));
}
__device__ __forceinline__ float2 up2(u64 v) {
    float2 f; asm("mov.b64 {%0, %1}, %2;" : "=f"(f.x), "=f"(f.y) : "l"(v)); return f;
}

// ---------------------------------------------------------------------------
// Fused GEMM kernel:
//   z == 0            : h = node_feats @ W_up           (tiles over blockIdx.x)
//   z >= 1, x == 0    : Wc[g] = W_lin[l] @ W_skip[g]/16 (g = z-1, single tile)
//   z >= 1, x >= 1    : helper blocks zero d_counts
// BM=128, BN=128, BK=16, 256 threads, 8x8 thread tile, f32x2 accumulation.
// ---------------------------------------------------------------------------
__global__ __launch_bounds__(256, 2) void gemm_fused_kernel(
    const float* __restrict__ node_feats,
    const float* __restrict__ W_up,
    const float* __restrict__ W_lin,
    const float* __restrict__ W_skip,
    int N, int NE)
{
    const float* A;
    const float* B;
    float* C;
    int M;
    float scale;
    int z = blockIdx.z;

    if (z == 0) {
        A = node_feats; B = W_up; C = d_h; M = N; scale = 1.0f;
    } else {
        if (blockIdx.x != 0) {
            // zero d_counts with the otherwise-idle blocks
            int nb  = gridDim.x - 1;
            int id  = (z - 1) * nb + (blockIdx.x - 1);
            int tot = (int)(gridDim.z - 1) * nb;
            for (int i = id * 256 + threadIdx.x; i < N; i += tot * 256)
                d_counts[i] = 0;
            return;
        }
        int g = z - 1;            // g = e*4 + l
        int l = g & 3;
        A = W_lin  + (size_t)l * 16384;
        B = W_skip + (size_t)g * 16384;
        C = d_Wc   + (size_t)g * 16384;
        M = 128; scale = 1.0f / 16.0f;
    }

    __shared__ float As[16 * AST];
    __shared__ float Bs[16 * 128];

    int tid = threadIdx.x;
    int ty = tid >> 4;      // 0..15 -> 8-row group
    int tx = tid & 15;      // 0..15 -> 4-col group (x2 halves)
    int row0 = blockIdx.x * 128;

    u64 acc[4][8];
    #pragma unroll
    for (int i = 0; i < 4; i++)
        #pragma unroll
        for (int j = 0; j < 8; j++) acc[i][j] = 0ull;

    for (int kc = 0; kc < 128; kc += 16) {
        #pragma unroll
        for (int i = 0; i < 8; i++) {
            int idx = tid + i * 256;
            int r = idx >> 4, kk = idx & 15;
            int row = row0 + r;
            As[kk * AST + r] = (row < M) ? A[(size_t)row * 128 + kc + kk] : 0.0f;
        }
        #pragma unroll
        for (int i = 0; i < 8; i++) {
            int idx = tid + i * 256;
            int kk = idx >> 7, d = idx & 127;
            Bs[kk * 128 + d] = B[(size_t)(kc + kk) * 128 + d];
        }
        __syncthreads();
        #pragma unroll
        for (int kk = 0; kk < 16; kk++) {
            float4 a0 = *(const float4*)&As[kk * AST + ty * 8];
            float4 a1 = *(const float4*)&As[kk * AST + ty * 8 + 4];
            float4 b0 = *(const float4*)&Bs[kk * 128 + tx * 4];
            float4 b1 = *(const float4*)&Bs[kk * 128 + 64 + tx * 4];
            u64 av[4];
            av[0] = ((const u64*)&a0)[0]; av[1] = ((const u64*)&a0)[1];
            av[2] = ((const u64*)&a1)[0]; av[3] = ((const u64*)&a1)[1];
            u64 bd[8] = { pk2(b0.x), pk2(b0.y), pk2(b0.z), pk2(b0.w),
                          pk2(b1.x), pk2(b1.y), pk2(b1.z), pk2(b1.w) };
            #pragma unroll
            for (int rp = 0; rp < 4; rp++)
                #pragma unroll
                for (int j = 0; j < 8; j++) fma2(acc[rp][j], av[rp], bd[j]);
        }
        __syncthreads();
    }

    #pragma unroll
    for (int rp = 0; rp < 4; rp++) {
        float2 p[8];
        #pragma unroll
        for (int j = 0; j < 8; j++) p[j] = up2(acc[rp][j]);
        int r0 = row0 + ty * 8 + rp * 2;
        if (r0 < M) {
            *(float4*)&C[(size_t)r0 * 128 + tx * 4] =
                make_float4(p[0].x * scale, p[1].x * scale, p[2].x * scale, p[3].x * scale);
            *(float4*)&C[(size_t)r0 * 128 + 64 + tx * 4] =
                make_float4(p[4].x * scale, p[5].x * scale, p[6].x * scale, p[7].x * scale);
        }
        if (r0 + 1 < M) {
            *(float4*)&C[(size_t)(r0 + 1) * 128 + tx * 4] =
                make_float4(p[0].y * scale, p[1].y * scale, p[2].y * scale, p[3].y * scale);
            *(float4*)&C[(size_t)(r0 + 1) * 128 + 64 + tx * 4] =
                make_float4(p[4].y * scale, p[5].y * scale, p[6].y * scale, p[7].y * scale);
        }
    }
}

// Fallback zeroing (only used if the fused grid has no helper blocks)
__global__ void zero_counts_kernel(int n) {
    int i = blockIdx.x * blockDim.x + threadIdx.x;
    if (i < n) d_counts[i] = 0;
}

// ---------------------------------------------------------------------------
// Counting sort of edges by receiver
// ---------------------------------------------------------------------------
__global__ void hist_kernel(const int* __restrict__ recv, int E) {
    int i = blockIdx.x * blockDim.x + threadIdx.x;
    if (i < E) atomicAdd(&d_counts[recv[i]], 1);
}

// block 0: warp-shuffle scan of d_counts -> d_offsets / d_cursor
// block 1: group nodes by element
__global__ void scan_elem_kernel(const int* __restrict__ node_elem, int N, int NE) {
    int tid = threadIdx.x;

    if (blockIdx.x == 1) {
        __shared__ int scnt[NE_MAX];
        if (tid < NE) scnt[tid] = 0;
        __syncthreads();
        for (int i = tid; i < N; i += blockDim.x) atomicAdd(&scnt[node_elem[i]], 1);
        __syncthreads();
        if (tid == 0) {
            int run = 0;
            for (int e = 0; e < NE; e++) { d_elem_off[e] = run; d_elem_cur[e] = run; run += scnt[e]; }
            d_elem_off[NE] = run;
        }
        __syncthreads();
        for (int i = tid; i < N; i += blockDim.x) {
            int pos = atomicAdd(&d_elem_cur[node_elem[i]], 1);
            d_node_by_elem[pos] = i;
        }
        return;
    }

    // block 0: scan (1024 threads x 6 elems = 6144 >= N_MAX)
    __shared__ int wtot[32];
    const int PER = 6;
    int lane = tid & 31, w = tid >> 5;
    int base = tid * PER;
    int cnt[PER];
    int run = 0;
    #pragma unroll
    for (int i = 0; i < PER; i++) {
        cnt[i] = (base + i < N) ? d_counts[base + i] : 0;
        run += cnt[i];
    }
    int ws = run;
    #pragma unroll
    for (int o = 1; o < 32; o <<= 1) {
        int t = __shfl_up_sync(0xffffffffu, ws, o);
        if (lane >= o) ws += t;
    }
    if (lane == 31) wtot[w] = ws;
    __syncthreads();
    if (w == 0) {
        int v = wtot[lane];
        #pragma unroll
        for (int o = 1; o < 32; o <<= 1) {
            int t = __shfl_up_sync(0xffffffffu, v, o);
            if (lane >= o) v += t;
        }
        wtot[lane] = v;
    }
    __syncthreads();
    int acc = (w ? wtot[w - 1] : 0) + (ws - run);  // exclusive prefix before chunk
    if (tid == 0) d_offsets[0] = 0;
    #pragma unroll
    for (int i = 0; i < PER; i++) {
        int idx = base + i;
        if (idx < N) {
            d_cursor[idx] = acc;       // segment start
            acc += cnt[i];
            d_offsets[idx + 1] = acc;
        }
    }
}

__global__ void scatter_kernel(const int* __restrict__ recv, int E) {
    int i = blockIdx.x * blockDim.x + threadIdx.x;
    if (i < E) {
        int pos = atomicAdd(&d_cursor[recv[i]], 1);
        d_sorted[pos] = i;
    }
}

// ---------------------------------------------------------------------------
// Edge accumulation: one CTA per node, 256 threads.
// Thread = (channel c = tid&127, parity par = tid>>7). Each thread owns all
// 16 lm accumulators for its channel; the two parities process alternating
// edges and are summed through shared memory at the end.
// l_of_lm: [0, 1,1,1, 2,2,2,2,2, 3,3,3,3,3,3,3]
// ---------------------------------------------------------------------------
__global__ __launch_bounds__(256) void edge_accum_kernel(
    const float* __restrict__ edge_attrs,   // [E,16]
    const float* __restrict__ edge_feats,   // [E,4,128]
    const int*   __restrict__ sender)       // [E]
{
    int n = blockIdx.x;
    int tid = threadIdx.x;
    int c = tid & 127;
    int par = tid >> 7;

    __shared__ float s_attr[16][16];
    __shared__ int   s_e[16];
    __shared__ int   s_send[16];
    __shared__ float s_part[16][128];

    float acc[16];
    #pragma unroll
    for (int i = 0; i < 16; i++) acc[i] = 0.0f;

    int beg = d_offsets[n];
    int end = d_offsets[n + 1];

    for (int base = beg; base < end; base += 16) {
        int m = end - base;
        if (m > 16) m = 16;
        if (tid < m) {
            int ee = d_sorted[base + tid];
            s_e[tid] = ee;
            s_send[tid] = sender[ee];
        }
        for (int i = tid; i < m * 16; i += 256) {
            int j = i >> 4;
            s_attr[j][i & 15] = edge_attrs[(size_t)d_sorted[base + j] * 16 + (i & 15)];
        }
        __syncthreads();

        for (int j = par; j < m; j += 2) {
            const float* efp = edge_feats + (size_t)s_e[j] * 512;
            float hs = d_h[(size_t)s_send[j] * 128 + c];
            float e0 = efp[c], e1 = efp[128 + c], e2 = efp[256 + c], e3 = efp[384 + c];
            float p0 = hs * e0, p1 = hs * e1, p2 = hs * e2, p3 = hs * e3;
            const float* at = s_attr[j];
            acc[0]  += p0 * at[0];
            acc[1]  += p1 * at[1];
            acc[2]  += p1 * at[2];
            acc[3]  += p1 * at[3];
            acc[4]  += p2 * at[4];
            acc[5]  += p2 * at[5];
            acc[6]  += p2 * at[6];
            acc[7]  += p2 * at[7];
            acc[8]  += p2 * at[8];
            acc[9]  += p3 * at[9];
            acc[10] += p3 * at[10];
            acc[11] += p3 * at[11];
            acc[12] += p3 * at[12];
            acc[13] += p3 * at[13];
            acc[14] += p3 * at[14];
            acc[15] += p3 * at[15];
        }
        __syncthreads();
    }

    if (par) {
        #pragma unroll
        for (int lm = 0; lm < 16; lm++) s_part[lm][c] = acc[lm];
    }
    __syncthreads();
    if (!par) {
        size_t ob = (size_t)n * 2048 + c;
        #pragma unroll
        for (int lm = 0; lm < 16; lm++)
            d_msg[ob + (size_t)lm * 128] = acc[lm] + s_part[lm][c];
    }
}

// ---------------------------------------------------------------------------
// Grouped output GEMM: group (e,l) has rows = cnt(e)*(2l+1); row r maps to
// msg row (node*16 + l^2 + r%(2l+1)). B = Wc[e*4+l]. Same 128x128x128 f32x2
// tiling; rows gathered through s_off.
// ---------------------------------------------------------------------------
__global__ __launch_bounds__(256, 2) void out_gemm_kernel(float* __restrict__ out)
{
    int g = blockIdx.y;
    int l = g & 3;
    int e = g >> 2;
    int tw = 2 * l + 1;
    int cbeg = d_elem_off[e];
    int rows = (d_elem_off[e + 1] - cbeg) * tw;
    const float* B = d_Wc + (size_t)g * 16384;

    __shared__ float As[16 * AST];
    __shared__ float Bs[16 * 128];
    __shared__ long  s_off[128];

    int tid = threadIdx.x;
    int ty = tid >> 4;
    int tx = tid & 15;

    for (int tile = blockIdx.x * 128; tile < rows; tile += gridDim.x * 128) {
        if (tid < 128) {
            int r = tile + tid;
            long off = -1;
            if (r < rows) {
                int node = d_node_by_elem[cbeg + r / tw];
                int lm = l * l + (r % tw);
                off = ((long)node * 16 + lm) * 128;
            }
            s_off[tid] = off;
        }
        __syncthreads();

        u64 acc[4][8];
        #pragma unroll
        for (int i = 0; i < 4; i++)
            #pragma unroll
            for (int j = 0; j < 8; j++) acc[i][j] = 0ull;

        for (int kc = 0; kc < 128; kc += 16) {
            #pragma unroll
            for (int i = 0; i < 8; i++) {
                int idx = tid + i * 256;
                int r = idx >> 4, kk = idx & 15;
                long off = s_off[r];
                As[kk * AST + r] = (off >= 0) ? d_msg[off + kc + kk] : 0.0f;
            }
            #pragma unroll
            for (int i = 0; i < 8; i++) {
                int idx = tid + i * 256;
                int kk = idx >> 7, d = idx & 127;
                Bs[kk * 128 + d] = B[(size_t)(kc + kk) * 128 + d];
            }
            __syncthreads();
            #pragma unroll
            for (int kk = 0; kk < 16; kk++) {
                float4 a0 = *(const float4*)&As[kk * AST + ty * 8];
                float4 a1 = *(const float4*)&As[kk * AST + ty * 8 + 4];
                float4 b0 = *(const float4*)&Bs[kk * 128 + tx * 4];
                float4 b1 = *(const float4*)&Bs[kk * 128 + 64 + tx * 4];
                u64 av[4];
                av[0] = ((const u64*)&a0)[0]; av[1] = ((const u64*)&a0)[1];
                av[2] = ((const u64*)&a1)[0]; av[3] = ((const u64*)&a1)[1];
                u64 bd[8] = { pk2(b0.x), pk2(b0.y), pk2(b0.z), pk2(b0.w),
                              pk2(b1.x), pk2(b1.y), pk2(b1.z), pk2(b1.w) };
                #pragma unroll
                for (int rp = 0; rp < 4; rp++)
                    #pragma unroll
                    for (int j = 0; j < 8; j++) fma2(acc[rp][j], av[rp], bd[j]);
            }
            __syncthreads();
        }

        #pragma unroll
        for (int rp = 0; rp < 4; rp++) {
            float2 p[8];
            #pragma unroll
            for (int j = 0; j < 8; j++) p[j] = up2(acc[rp][j]);
            int r0 = ty * 8 + rp * 2;
            long off0 = s_off[r0];
            long off1 = s_off[r0 + 1];
            if (off0 >= 0) {
                *(float4*)&out[off0 + tx * 4] =
                    make_float4(p[0].x, p[1].x, p[2].x, p[3].x);
                *(float4*)&out[off0 + 64 + tx * 4] =
                    make_float4(p[4].x, p[5].x, p[6].x, p[7].x);
            }
            if (off1 >= 0) {
                *(float4*)&out[off1 + tx * 4] =
                    make_float4(p[0].y, p[1].y, p[2].y, p[3].y);
                *(float4*)&out[off1 + 64 + tx * 4] =
                    make_float4(p[4].y, p[5].y, p[6].y, p[7].y);
            }
        }
        __syncthreads();   // protect s_off before next tile
    }
}

// ---------------------------------------------------------------------------
// Launch
// ---------------------------------------------------------------------------
extern "C" void kernel_launch(void* const* d_in, const int* in_sizes, int n_in,
                              void* d_out, int out_size)
{
    const float* node_feats = (const float*)d_in[0];   // [N,128]
    const float* edge_attrs = (const float*)d_in[1];   // [E,16]
    const float* edge_feats = (const float*)d_in[2];   // [E,512]
    const float* W_up       = (const float*)d_in[3];   // [128,128]
    const float* W_lin      = (const float*)d_in[4];   // [4,128,128]
    const float* W_skip     = (const float*)d_in[5];   // [NE,4,128,128]
    const int*   edge_index = (const int*)d_in[6];     // [2,E]
    const int*   node_elem  = (const int*)d_in[7];     // [N]

    int N  = in_sizes[7];
    int E  = in_sizes[1] / 16;
    int NE = in_sizes[5] / (4 * 128 * 128);

    const int* sender = edge_index;
    const int* recv   = edge_index + E;

    int gx = (N + 127) / 128;

    // 1. h = node_feats @ W_up  +  Wc = W_lin @ W_skip / 16  +  zero counts
    gemm_fused_kernel<<<dim3(gx, 1, 1 + NE * 4), 256>>>(
        node_feats, W_up, W_lin, W_skip, N, NE);
    if (gx < 2)   // no helper blocks existed: zero counts explicitly
        zero_counts_kernel<<<(N + 255) / 256, 256>>>(N);

    // 2. counting-sort edges by receiver (+ element grouping in parallel)
    hist_kernel<<<(E + 255) / 256, 256>>>(recv, E);
    scan_elem_kernel<<<2, 1024>>>(node_elem, N, NE);
    scatter_kernel<<<(E + 255) / 256, 256>>>(recv, E);

    // 3. per-node edge accumulation -> msg
    edge_accum_kernel<<<N, 256>>>(edge_attrs, edge_feats, sender);

    // 4. grouped output GEMM: out = msg @ Wc[elem, l]
    out_gemm_kernel<<<dim3(32, NE * 4), 256>>>((float*)d_out);
}

// round 5
// speedup vs baseline: 1.1743x; 1.0293x over previous
#include <cuda_runtime.h>
#include <cstdint>

// ---------------------------------------------------------------------------
// MACE invariant message passing, fused:
//   h   = node_feats @ W_up
//   m   = h[sender] * edge_attrs * edge_feats[l_of_lm]   (per edge)
//   msg = segment_sum over receiver
//   out = msg @ ( W_lin[l] @ W_skip[elem,l] / 16 )       (grouped by element)
// ---------------------------------------------------------------------------

typedef unsigned long long u64;

#define N_MAX 6144
#define E_MAX 131072
#define NE_MAX 16
#define AST 132   // As row stride (floats)

// Static device scratch (allocation-free per harness rules)
__device__ float d_h[(size_t)N_MAX * 128];
__device__ float d_msg[(size_t)N_MAX * 16 * 128];
__device__ float d_Wc[(size_t)NE_MAX * 4 * 128 * 128];
__device__ int   d_sorted[E_MAX];
__device__ int   d_counts[N_MAX];
__device__ int   d_offsets[N_MAX + 1];
__device__ int   d_cursor[N_MAX];
__device__ int   d_node_by_elem[N_MAX];
__device__ int   d_elem_off[NE_MAX + 1];
__device__ int   d_elem_cur[NE_MAX];
__device__ int   d_tile_off[NE_MAX * 4 + 1];
__device__ int   d_tile_ctr;

// --------------------------- f32x2 helpers ---------------------------------
__device__ __forceinline__ u64 pk2(float x) {
    u64 r; asm("mov.b64 %0, {%1, %1};" : "=l"(r) : "f"(x)); return r;
}
__device__ __forceinline__ void fma2(u64& d, u64 a, u64 b) {
    asm("fma.rn.f32x2 %0, %1, %2, %0;" : "+l"(d) : "l"(a), "l"(b));
}
__device__ __forceinline__ float2 up2(u64 v) {
    float2 f; asm("mov.b64 {%0, %1}, %2;" : "=f"(f.x), "=f"(f.y) : "l"(v)); return f;
}

// ---------------------------------------------------------------------------
__global__ void zero_counts_kernel(int n) {
    int i = blockIdx.x * blockDim.x + threadIdx.x;
    if (i < n) d_counts[i] = 0;
}

// ---------------------------------------------------------------------------
// Fused GEMM kernel:
//   z == 0            : h = node_feats @ W_up           (tiles over blockIdx.x)
//   z >= 1, x == 0    : Wc[g] = W_lin[l] @ W_skip[g]/16 (g = z-1, single tile)
//   z >= 1, x >= 1    : helper blocks run the receiver histogram
// BM=128, BN=128, BK=16, 256 threads, 8x8 thread tile, f32x2 accumulation.
// ---------------------------------------------------------------------------
__global__ __launch_bounds__(256, 2) void gemm_fused_kernel(
    const float* __restrict__ node_feats,
    const float* __restrict__ W_up,
    const float* __restrict__ W_lin,
    const float* __restrict__ W_skip,
    const int*   __restrict__ recv,
    int N, int E, int NE)
{
    const float* A;
    const float* B;
    float* C;
    int M;
    float scale;
    int z = blockIdx.z;

    if (z == 0) {
        A = node_feats; B = W_up; C = d_h; M = N; scale = 1.0f;
    } else {
        if (blockIdx.x != 0) {
            // histogram of receivers with the otherwise-idle blocks
            int nb  = gridDim.x - 1;
            int id  = (z - 1) * nb + (blockIdx.x - 1);
            int tot = (int)(gridDim.z - 1) * nb;
            for (int i = id * 256 + threadIdx.x; i < E; i += tot * 256)
                atomicAdd(&d_counts[recv[i]], 1);
            return;
        }
        int g = z - 1;            // g = e*4 + l
        int l = g & 3;
        A = W_lin  + (size_t)l * 16384;
        B = W_skip + (size_t)g * 16384;
        C = d_Wc   + (size_t)g * 16384;
        M = 128; scale = 1.0f / 16.0f;
    }

    __shared__ float As[16 * AST];
    __shared__ float Bs[16 * 128];

    int tid = threadIdx.x;
    int ty = tid >> 4;      // 0..15 -> 8-row group
    int tx = tid & 15;      // 0..15 -> 4-col group (x2 halves)
    int row0 = blockIdx.x * 128;

    u64 acc[4][8];
    #pragma unroll
    for (int i = 0; i < 4; i++)
        #pragma unroll
        for (int j = 0; j < 8; j++) acc[i][j] = 0ull;

    for (int kc = 0; kc < 128; kc += 16) {
        #pragma unroll
        for (int i = 0; i < 8; i++) {
            int idx = tid + i * 256;
            int r = idx >> 4, kk = idx & 15;
            int row = row0 + r;
            As[kk * AST + r] = (row < M) ? A[(size_t)row * 128 + kc + kk] : 0.0f;
        }
        #pragma unroll
        for (int i = 0; i < 8; i++) {
            int idx = tid + i * 256;
            int kk = idx >> 7, d = idx & 127;
            Bs[kk * 128 + d] = B[(size_t)(kc + kk) * 128 + d];
        }
        __syncthreads();
        #pragma unroll
        for (int kk = 0; kk < 16; kk++) {
            float4 a0 = *(const float4*)&As[kk * AST + ty * 8];
            float4 a1 = *(const float4*)&As[kk * AST + ty * 8 + 4];
            float4 b0 = *(const float4*)&Bs[kk * 128 + tx * 4];
            float4 b1 = *(const float4*)&Bs[kk * 128 + 64 + tx * 4];
            u64 av[4];
            av[0] = ((const u64*)&a0)[0]; av[1] = ((const u64*)&a0)[1];
            av[2] = ((const u64*)&a1)[0]; av[3] = ((const u64*)&a1)[1];
            float bs[8] = { b0.x, b0.y, b0.z, b0.w, b1.x, b1.y, b1.z, b1.w };
            #pragma unroll
            for (int j = 0; j < 8; j++) {
                u64 b2 = pk2(bs[j]);
                #pragma unroll
                for (int rp = 0; rp < 4; rp++) fma2(acc[rp][j], av[rp], b2);
            }
        }
        __syncthreads();
    }

    #pragma unroll
    for (int rp = 0; rp < 4; rp++) {
        float2 p[8];
        #pragma unroll
        for (int j = 0; j < 8; j++) p[j] = up2(acc[rp][j]);
        int r0 = row0 + ty * 8 + rp * 2;
        if (r0 < M) {
            *(float4*)&C[(size_t)r0 * 128 + tx * 4] =
                make_float4(p[0].x * scale, p[1].x * scale, p[2].x * scale, p[3].x * scale);
            *(float4*)&C[(size_t)r0 * 128 + 64 + tx * 4] =
                make_float4(p[4].x * scale, p[5].x * scale, p[6].x * scale, p[7].x * scale);
        }
        if (r0 + 1 < M) {
            *(float4*)&C[(size_t)(r0 + 1) * 128 + tx * 4] =
                make_float4(p[0].y * scale, p[1].y * scale, p[2].y * scale, p[3].y * scale);
            *(float4*)&C[(size_t)(r0 + 1) * 128 + 64 + tx * 4] =
                make_float4(p[4].y * scale, p[5].y * scale, p[6].y * scale, p[7].y * scale);
        }
    }
}

// Fallback hist (only if the fused grid had no helper blocks)
__global__ void hist_kernel(const int* __restrict__ recv, int E) {
    int i = blockIdx.x * blockDim.x + threadIdx.x;
    if (i < E) atomicAdd(&d_counts[recv[i]], 1);
}

// ---------------------------------------------------------------------------
// block 0: warp-shuffle scan of d_counts -> d_offsets / d_cursor
// block 1: group nodes by element; build per-(e,l) tile prefix; reset tile ctr
// ---------------------------------------------------------------------------
__global__ void scan_elem_kernel(const int* __restrict__ node_elem, int N, int NE) {
    int tid = threadIdx.x;

    if (blockIdx.x == 1) {
        __shared__ int scnt[NE_MAX];
        if (tid < NE) scnt[tid] = 0;
        __syncthreads();
        for (int i = tid; i < N; i += blockDim.x) atomicAdd(&scnt[node_elem[i]], 1);
        __syncthreads();
        if (tid == 0) {
            int run = 0;
            for (int e = 0; e < NE; e++) { d_elem_off[e] = run; d_elem_cur[e] = run; run += scnt[e]; }
            d_elem_off[NE] = run;
            // tile prefix for the output GEMM work queue
            int tp = 0;
            for (int g = 0; g < NE * 4; g++) {
                int l = g & 3;
                int rows = scnt[g >> 2] * (2 * l + 1);
                d_tile_off[g] = tp;
                tp += (rows + 127) >> 7;
            }
            d_tile_off[NE * 4] = tp;
            d_tile_ctr = 0;
        }
        __syncthreads();
        for (int i = tid; i < N; i += blockDim.x) {
            int pos = atomicAdd(&d_elem_cur[node_elem[i]], 1);
            d_node_by_elem[pos] = i;
        }
        return;
    }

    // block 0: scan (1024 threads x 6 elems = 6144 >= N_MAX)
    __shared__ int wtot[32];
    const int PER = 6;
    int lane = tid & 31, w = tid >> 5;
    int base = tid * PER;
    int cnt[PER];
    int run = 0;
    #pragma unroll
    for (int i = 0; i < PER; i++) {
        cnt[i] = (base + i < N) ? d_counts[base + i] : 0;
        run += cnt[i];
    }
    int ws = run;
    #pragma unroll
    for (int o = 1; o < 32; o <<= 1) {
        int t = __shfl_up_sync(0xffffffffu, ws, o);
        if (lane >= o) ws += t;
    }
    if (lane == 31) wtot[w] = ws;
    __syncthreads();
    if (w == 0) {
        int v = wtot[lane];
        #pragma unroll
        for (int o = 1; o < 32; o <<= 1) {
            int t = __shfl_up_sync(0xffffffffu, v, o);
            if (lane >= o) v += t;
        }
        wtot[lane] = v;
    }
    __syncthreads();
    int acc = (w ? wtot[w - 1] : 0) + (ws - run);
    if (tid == 0) d_offsets[0] = 0;
    #pragma unroll
    for (int i = 0; i < PER; i++) {
        int idx = base + i;
        if (idx < N) {
            d_cursor[idx] = acc;
            acc += cnt[i];
            d_offsets[idx + 1] = acc;
        }
    }
}

__global__ void scatter_kernel(const int* __restrict__ recv, int E) {
    int i = blockIdx.x * blockDim.x + threadIdx.x;
    if (i < E) {
        int pos = atomicAdd(&d_cursor[recv[i]], 1);
        d_sorted[pos] = i;
    }
}

// ---------------------------------------------------------------------------
// Edge accumulation: one CTA per node, 256 threads.
// Thread = (channel c = tid&127, parity par = tid>>7). Each thread owns all
// 16 lm accumulators for its channel; parities process alternating edges
// with explicit next-edge prefetch, then combine through shared memory.
// l_of_lm: [0, 1,1,1, 2,2,2,2,2, 3,3,3,3,3,3,3]
// ---------------------------------------------------------------------------
__global__ __launch_bounds__(256) void edge_accum_kernel(
    const float* __restrict__ edge_attrs,   // [E,16]
    const float* __restrict__ edge_feats,   // [E,4,128]
    const int*   __restrict__ sender)       // [E]
{
    int n = blockIdx.x;
    int tid = threadIdx.x;
    int c = tid & 127;
    int par = tid >> 7;

    __shared__ float s_attr[32][16];
    __shared__ int   s_e[32];
    __shared__ int   s_send[32];
    __shared__ float s_part[16][128];

    float acc[16];
    #pragma unroll
    for (int i = 0; i < 16; i++) acc[i] = 0.0f;

    int beg = d_offsets[n];
    int end = d_offsets[n + 1];

    for (int base = beg; base < end; base += 32) {
        int m = end - base;
        if (m > 32) m = 32;
        if (tid < m) {
            int ee = d_sorted[base + tid];
            s_e[tid] = ee;
            s_send[tid] = sender[ee];
        }
        for (int i = tid; i < m * 16; i += 256) {
            int j = i >> 4;
            s_attr[j][i & 15] = edge_attrs[(size_t)d_sorted[base + j] * 16 + (i & 15)];
        }
        __syncthreads();

        int j = par;
        float e0 = 0.f, e1 = 0.f, e2 = 0.f, e3 = 0.f, hs = 0.f;
        if (j < m) {
            const float* efp = edge_feats + (size_t)s_e[j] * 512;
            e0 = efp[c]; e1 = efp[128 + c]; e2 = efp[256 + c]; e3 = efp[384 + c];
            hs = d_h[(size_t)s_send[j] * 128 + c];
        }
        while (j < m) {
            int jn = j + 2;
            float f0 = 0.f, f1 = 0.f, f2 = 0.f, f3 = 0.f, hn = 0.f;
            if (jn < m) {
                const float* efp = edge_feats + (size_t)s_e[jn] * 512;
                f0 = efp[c]; f1 = efp[128 + c]; f2 = efp[256 + c]; f3 = efp[384 + c];
                hn = d_h[(size_t)s_send[jn] * 128 + c];
            }
            const float* at = s_attr[j];
            float p0 = hs * e0, p1 = hs * e1, p2 = hs * e2, p3 = hs * e3;
            acc[0]  += p0 * at[0];
            acc[1]  += p1 * at[1];
            acc[2]  += p1 * at[2];
            acc[3]  += p1 * at[3];
            acc[4]  += p2 * at[4];
            acc[5]  += p2 * at[5];
            acc[6]  += p2 * at[6];
            acc[7]  += p2 * at[7];
            acc[8]  += p2 * at[8];
            acc[9]  += p3 * at[9];
            acc[10] += p3 * at[10];
            acc[11] += p3 * at[11];
            acc[12] += p3 * at[12];
            acc[13] += p3 * at[13];
            acc[14] += p3 * at[14];
            acc[15] += p3 * at[15];
            j = jn; e0 = f0; e1 = f1; e2 = f2; e3 = f3; hs = hn;
        }
        __syncthreads();
    }

    if (par) {
        #pragma unroll
        for (int lm = 0; lm < 16; lm++) s_part[lm][c] = acc[lm];
    }
    __syncthreads();
    if (!par) {
        size_t ob = (size_t)n * 2048 + c;
        #pragma unroll
        for (int lm = 0; lm < 16; lm++)
            d_msg[ob + (size_t)lm * 128] = acc[lm] + s_part[lm][c];
    }
}

// ---------------------------------------------------------------------------
// Grouped output GEMM, persistent CTAs + global tile queue.
// Tile t -> group g via tile prefix; group (e,l) has rows = cnt(e)*(2l+1);
// row r maps to msg row (node*16 + l*l + r%(2l+1)). B = Wc[g] (L2-resident).
// ---------------------------------------------------------------------------
__global__ __launch_bounds__(256, 2) void out_gemm_kernel(float* __restrict__ out, int NE)
{
    __shared__ float As[16 * AST];
    __shared__ float Bs[16 * 128];
    __shared__ int   s_off[128];
    __shared__ int   s_toff[NE_MAX * 4 + 1];
    __shared__ int   s_eoff[NE_MAX + 1];
    __shared__ int   s_tile;

    int tid = threadIdx.x;
    int NG = NE * 4;
    if (tid <= NG) s_toff[tid] = d_tile_off[tid];
    if (tid <= NE) s_eoff[tid] = d_elem_off[tid];
    __syncthreads();
    int ntiles = s_toff[NG];

    int ty = tid >> 4;
    int tx = tid & 15;

    while (true) {
        if (tid == 0) s_tile = atomicAdd(&d_tile_ctr, 1);
        __syncthreads();
        int t = s_tile;
        if (t >= ntiles) break;

        int g = 0;
        while (s_toff[g + 1] <= t) g++;
        int l = g & 3;
        int e = g >> 2;
        int tw = 2 * l + 1;
        int cbeg = s_eoff[e];
        int rows = (s_eoff[e + 1] - cbeg) * tw;
        int tile = (t - s_toff[g]) * 128;
        const float* B = d_Wc + (size_t)g * 16384;

        if (tid < 128) {
            int r = tile + tid;
            int off = -1;
            if (r < rows) {
                int node = d_node_by_elem[cbeg + r / tw];
                int lm = l * l + (r % tw);
                off = (node * 16 + lm) * 128;
            }
            s_off[tid] = off;
        }
        __syncthreads();

        u64 acc[4][8];
        #pragma unroll
        for (int i = 0; i < 4; i++)
            #pragma unroll
            for (int j = 0; j < 8; j++) acc[i][j] = 0ull;

        for (int kc = 0; kc < 128; kc += 16) {
            #pragma unroll
            for (int i = 0; i < 8; i++) {
                int idx = tid + i * 256;
                int r = idx >> 4, kk = idx & 15;
                int off = s_off[r];
                As[kk * AST + r] = (off >= 0) ? d_msg[(size_t)off + kc + kk] : 0.0f;
            }
            #pragma unroll
            for (int i = 0; i < 8; i++) {
                int idx = tid + i * 256;
                int kk = idx >> 7, d = idx & 127;
                Bs[kk * 128 + d] = B[(size_t)(kc + kk) * 128 + d];
            }
            __syncthreads();
            #pragma unroll
            for (int kk = 0; kk < 16; kk++) {
                float4 a0 = *(const float4*)&As[kk * AST + ty * 8];
                float4 a1 = *(const float4*)&As[kk * AST + ty * 8 + 4];
                float4 b0 = *(const float4*)&Bs[kk * 128 + tx * 4];
                float4 b1 = *(const float4*)&Bs[kk * 128 + 64 + tx * 4];
                u64 av[4];
                av[0] = ((const u64*)&a0)[0]; av[1] = ((const u64*)&a0)[1];
                av[2] = ((const u64*)&a1)[0]; av[3] = ((const u64*)&a1)[1];
                float bs[8] = { b0.x, b0.y, b0.z, b0.w, b1.x, b1.y, b1.z, b1.w };
                #pragma unroll
                for (int j = 0; j < 8; j++) {
                    u64 b2 = pk2(bs[j]);
                    #pragma unroll
                    for (int rp = 0; rp < 4; rp++) fma2(acc[rp][j], av[rp], b2);
                }
            }
            __syncthreads();
        }

        #pragma unroll
        for (int rp = 0; rp < 4; rp++) {
            float2 p[8];
            #pragma unroll
            for (int j = 0; j < 8; j++) p[j] = up2(acc[rp][j]);
            int r0 = ty * 8 + rp * 2;
            int off0 = s_off[r0];
            int off1 = s_off[r0 + 1];
            if (off0 >= 0) {
                *(float4*)&out[(size_t)off0 + tx * 4] =
                    make_float4(p[0].x, p[1].x, p[2].x, p[3].x);
                *(float4*)&out[(size_t)off0 + 64 + tx * 4] =
                    make_float4(p[4].x, p[5].x, p[6].x, p[7].x);
            }
            if (off1 >= 0) {
                *(float4*)&out[(size_t)off1 + tx * 4] =
                    make_float4(p[0].y, p[1].y, p[2].y, p[3].y);
                *(float4*)&out[(size_t)off1 + 64 + tx * 4] =
                    make_float4(p[4].y, p[5].y, p[6].y, p[7].y);
            }
        }
        __syncthreads();   // protect s_off/s_tile before next tile
    }
}

// ---------------------------------------------------------------------------
// Launch
// ---------------------------------------------------------------------------
extern "C" void kernel_launch(void* const* d_in, const int* in_sizes, int n_in,
                              void* d_out, int out_size)
{
    const float* node_feats = (const float*)d_in[0];   // [N,128]
    const float* edge_attrs = (const float*)d_in[1];   // [E,16]
    const float* edge_feats = (const float*)d_in[2];   // [E,512]
    const float* W_up       = (const float*)d_in[3];   // [128,128]
    const float* W_lin      = (const float*)d_in[4];   // [4,128,128]
    const float* W_skip     = (const float*)d_in[5];   // [NE,4,128,128]
    const int*   edge_index = (const int*)d_in[6];     // [2,E]
    const int*   node_elem  = (const int*)d_in[7];     // [N]

    int N  = in_sizes[7];
    int E  = in_sizes[1] / 16;
    int NE = in_sizes[5] / (4 * 128 * 128);

    const int* sender = edge_index;
    const int* recv   = edge_index + E;

    int gx = (N + 127) / 128;

    // 0. zero receiver counts (must precede histogram inside gemm_fused)
    zero_counts_kernel<<<(N + 255) / 256, 256>>>(N);

    // 1. h = node_feats @ W_up  +  Wc = W_lin @ W_skip / 16  +  hist (helpers)
    gemm_fused_kernel<<<dim3(gx, 1, 1 + NE * 4), 256>>>(
        node_feats, W_up, W_lin, W_skip, recv, N, E, NE);
    if (gx < 2)   // no helper blocks existed: run hist explicitly
        hist_kernel<<<(E + 255) / 256, 256>>>(recv, E);

    // 2. scan + element grouping + tile-queue setup
    scan_elem_kernel<<<2, 1024>>>(node_elem, N, NE);
    scatter_kernel<<<(E + 255) / 256, 256>>>(recv, E);

    // 3. per-node edge accumulation -> msg
    edge_accum_kernel<<<N, 256>>>(edge_attrs, edge_feats, sender);

    // 4. grouped output GEMM: out = msg @ Wc[elem, l]  (persistent queue)
    out_gemm_kernel<<<296, 256>>>((float*)d_out, NE);
}

// round 8
// speedup vs baseline: 1.2870x; 1.0960x over previous
#include <cuda_runtime.h>
#include <cuda_bf16.h>
#include <cstdint>

// ---------------------------------------------------------------------------
// MACE invariant message passing:
//   h   = node_feats @ W_up
//   m   = h[sender] * edge_attrs * edge_feats[l_of_lm]   (per edge)
//   msg = segment_sum over receiver
//   out = msg @ ( W_lin[l] @ W_skip[elem,l] / 16 )       (grouped by element)
// Output GEMM: warp-level mma.sync bf16 (HMMA) with hi/lo compensation.
// ---------------------------------------------------------------------------

typedef unsigned long long u64;

#define N_MAX 6144
#define E_MAX 131072
#define NE_MAX 16
#define NG_MAX (NE_MAX * 4)
#define AST 132   // As row stride (floats) in the scalar GEMM

// Static device scratch (allocation-free per harness rules)
__device__ float d_h[(size_t)N_MAX * 128];
__device__ float d_msg[(size_t)N_MAX * 16 * 128];
__device__ __nv_bfloat16 d_WcT_hi[(size_t)NG_MAX * 128 * 128];
__device__ __nv_bfloat16 d_WcT_lo[(size_t)NG_MAX * 128 * 128];
__device__ int   d_sorted[E_MAX];
__device__ int   d_counts[N_MAX];          // zero-init; scan re-zeroes after use
__device__ int   d_offsets[N_MAX + 1];
__device__ int   d_cursor[N_MAX];
__device__ int   d_node_by_elem[N_MAX];
__device__ int   d_elem_off[NE_MAX + 1];
__device__ int   d_elem_cur[NE_MAX];
__device__ int   d_tile_off[NG_MAX + 1];
__device__ int   d_tile_ctr;

// --------------------------- helpers ---------------------------------------
__device__ __forceinline__ uint32_t smem_u32(const void* p) {
    uint32_t a;
    asm("{ .reg .u64 t; cvta.to.shared.u64 t, %1; cvt.u32.u64 %0, t; }"
        : "=r"(a) : "l"(p));
    return a;
}

#define LDSM4(r0, r1, r2, r3, addr) \
    asm volatile("ldmatrix.sync.aligned.m8n8.x4.shared.b16 {%0,%1,%2,%3}, [%4];" \
        : "=r"(r0), "=r"(r1), "=r"(r2), "=r"(r3) : "r"(addr))

#define MMA16816(c, a, b) \
    asm volatile("mma.sync.aligned.m16n8k16.row.col.f32.bf16.bf16.f32 " \
        "{%0,%1,%2,%3}, {%4,%5,%6,%7}, {%8,%9}, {%0,%1,%2,%3};" \
        : "+f"((c)[0]), "+f"((c)[1]), "+f"((c)[2]), "+f"((c)[3]) \
        : "r"((a)[0]), "r"((a)[1]), "r"((a)[2]), "r"((a)[3]), \
          "r"((b)[0]), "r"((b)[1]))

// ---------------------------------------------------------------------------
// Fused GEMM kernel (scalar fp32):
//   z == 0         : h = node_feats @ W_up           (tiles over blockIdx.x)
//   z >= 1, x == 0 : WcT[g] = transpose(W_lin[l] @ W_skip[g] / 16) as bf16 hi/lo
//   z >= 1, x >= 1 : helper blocks run the receiver histogram
// ---------------------------------------------------------------------------
__global__ __launch_bounds__(256, 2) void gemm_fused_kernel(
    const float* __restrict__ node_feats,
    const float* __restrict__ W_up,
    const float* __restrict__ W_lin,
    const float* __restrict__ W_skip,
    const int*   __restrict__ recv,
    int N, int E, int NE)
{
    const float* A;
    const float* B;
    int M;
    float scale;
    int z = blockIdx.z;
    int g = z - 1;

    if (z == 0) {
        A = node_feats; B = W_up; M = N; scale = 1.0f;
    } else {
        if (blockIdx.x != 0) {
            int nb  = gridDim.x - 1;
            int id  = (z - 1) * nb + (blockIdx.x - 1);
            int tot = (int)(gridDim.z - 1) * nb;
            for (int i = id * 256 + threadIdx.x; i < E; i += tot * 256)
                atomicAdd(&d_counts[recv[i]], 1);
            return;
        }
        int l = g & 3;
        A = W_lin  + (size_t)l * 16384;
        B = W_skip + (size_t)g * 16384;
        M = 128; scale = 1.0f / 16.0f;
    }

    __shared__ float As[16 * AST];
    __shared__ float Bs[16 * 128];

    int tid = threadIdx.x;
    int ty = tid >> 4;      // 0..15 -> 8-row group
    int tx = tid & 15;      // 0..15 -> 4-col group (x2 halves)
    int row0 = blockIdx.x * 128;

    float acc[8][8];
    #pragma unroll
    for (int i = 0; i < 8; i++)
        #pragma unroll
        for (int j = 0; j < 8; j++) acc[i][j] = 0.0f;

    for (int kc = 0; kc < 128; kc += 16) {
        #pragma unroll
        for (int i = 0; i < 8; i++) {
            int idx = tid + i * 256;
            int r = idx >> 4, kk = idx & 15;
            int row = row0 + r;
            As[kk * AST + r] = (row < M) ? A[(size_t)row * 128 + kc + kk] : 0.0f;
        }
        #pragma unroll
        for (int i = 0; i < 8; i++) {
            int idx = tid + i * 256;
            int kk = idx >> 7, d = idx & 127;
            Bs[kk * 128 + d] = B[(size_t)(kc + kk) * 128 + d];
        }
        __syncthreads();
        #pragma unroll
        for (int kk = 0; kk < 16; kk++) {
            float4 a0 = *(const float4*)&As[kk * AST + ty * 8];
            float4 a1 = *(const float4*)&As[kk * AST + ty * 8 + 4];
            float4 b0 = *(const float4*)&Bs[kk * 128 + tx * 4];
            float4 b1 = *(const float4*)&Bs[kk * 128 + 64 + tx * 4];
            float av[8] = {a0.x, a0.y, a0.z, a0.w, a1.x, a1.y, a1.z, a1.w};
            float bv[8] = {b0.x, b0.y, b0.z, b0.w, b1.x, b1.y, b1.z, b1.w};
            #pragma unroll
            for (int i = 0; i < 8; i++)
                #pragma unroll
                for (int j = 0; j < 8; j++) acc[i][j] += av[i] * bv[j];
        }
        __syncthreads();
    }

    if (z == 0) {
        #pragma unroll
        for (int i = 0; i < 8; i++) {
            int row = row0 + ty * 8 + i;
            if (row < M) {
                *(float4*)&d_h[(size_t)row * 128 + tx * 4] =
                    make_float4(acc[i][0], acc[i][1], acc[i][2], acc[i][3]);
                *(float4*)&d_h[(size_t)row * 128 + 64 + tx * 4] =
                    make_float4(acc[i][4], acc[i][5], acc[i][6], acc[i][7]);
            }
        }
    } else {
        // transposed bf16 hi/lo write: WcT[g][d][c], c = Wc row, d = Wc col
        #pragma unroll
        for (int i = 0; i < 8; i++) {
            int c = ty * 8 + i;
            #pragma unroll
            for (int j = 0; j < 8; j++) {
                int d = (j < 4) ? (tx * 4 + j) : (64 + tx * 4 + (j - 4));
                float v = acc[i][j] * scale;
                __nv_bfloat16 hv = __float2bfloat16_rn(v);
                float lv = v - __bfloat162float(hv);
                size_t o = ((size_t)g * 128 + d) * 128 + c;
                d_WcT_hi[o] = hv;
                d_WcT_lo[o] = __float2bfloat16_rn(lv);
            }
        }
    }
}

// Fallback hist (only if the fused grid had no helper blocks)
__global__ void hist_kernel(const int* __restrict__ recv, int E) {
    int i = blockIdx.x * blockDim.x + threadIdx.x;
    if (i < E) atomicAdd(&d_counts[recv[i]], 1);
}

// ---------------------------------------------------------------------------
// block 0: warp-shuffle scan of d_counts -> d_offsets / d_cursor, then
//          RE-ZEROES d_counts (keeps the zero invariant across graph replays)
// block 1: group nodes by element; tile prefix; reset tile counter
// ---------------------------------------------------------------------------
__global__ void scan_elem_kernel(const int* __restrict__ node_elem, int N, int NE) {
    int tid = threadIdx.x;

    if (blockIdx.x == 1) {
        __shared__ int scnt[NE_MAX];
        if (tid < NE) scnt[tid] = 0;
        __syncthreads();
        for (int i = tid; i < N; i += blockDim.x) atomicAdd(&scnt[node_elem[i]], 1);
        __syncthreads();
        if (tid == 0) {
            int run = 0;
            for (int e = 0; e < NE; e++) { d_elem_off[e] = run; d_elem_cur[e] = run; run += scnt[e]; }
            d_elem_off[NE] = run;
            int tp = 0;
            for (int g = 0; g < NE * 4; g++) {
                int l = g & 3;
                int rows = scnt[g >> 2] * (2 * l + 1);
                d_tile_off[g] = tp;
                tp += (rows + 127) >> 7;
            }
            d_tile_off[NE * 4] = tp;
            d_tile_ctr = 0;
        }
        __syncthreads();
        for (int i = tid; i < N; i += blockDim.x) {
            int pos = atomicAdd(&d_elem_cur[node_elem[i]], 1);
            d_node_by_elem[pos] = i;
        }
        return;
    }

    // block 0: scan (1024 threads x 6 elems = 6144 >= N_MAX)
    __shared__ int wtot[32];
    const int PER = 6;
    int lane = tid & 31, w = tid >> 5;
    int base = tid * PER;
    int cnt[PER];
    int run = 0;
    #pragma unroll
    for (int i = 0; i < PER; i++) {
        cnt[i] = (base + i < N) ? d_counts[base + i] : 0;
        run += cnt[i];
    }
    int ws = run;
    #pragma unroll
    for (int o = 1; o < 32; o <<= 1) {
        int t = __shfl_up_sync(0xffffffffu, ws, o);
        if (lane >= o) ws += t;
    }
    if (lane == 31) wtot[w] = ws;
    __syncthreads();
    if (w == 0) {
        int v = wtot[lane];
        #pragma unroll
        for (int o = 1; o < 32; o <<= 1) {
            int t = __shfl_up_sync(0xffffffffu, v, o);
            if (lane >= o) v += t;
        }
        wtot[lane] = v;
    }
    __syncthreads();
    int acc = (w ? wtot[w - 1] : 0) + (ws - run);
    if (tid == 0) d_offsets[0] = 0;
    #pragma unroll
    for (int i = 0; i < PER; i++) {
        int idx = base + i;
        if (idx < N) {
            d_cursor[idx] = acc;
            acc += cnt[i];
            d_offsets[idx + 1] = acc;
            d_counts[idx] = 0;     // restore zero invariant for next replay
        }
    }
}

__global__ void scatter_kernel(const int* __restrict__ recv, int E) {
    int i = blockIdx.x * blockDim.x + threadIdx.x;
    if (i < E) {
        int pos = atomicAdd(&d_cursor[recv[i]], 1);
        d_sorted[pos] = i;
    }
}

// ---------------------------------------------------------------------------
// Edge accumulation: one CTA per node, 256 threads.
// Thread = (channel c = tid&127, parity par = tid>>7), 16 lm accs per thread,
// parities process alternating edges with next-edge prefetch, combined via smem.
// l_of_lm: [0, 1,1,1, 2,2,2,2,2, 3,3,3,3,3,3,3]
// ---------------------------------------------------------------------------
__global__ __launch_bounds__(256) void edge_accum_kernel(
    const float* __restrict__ edge_attrs,   // [E,16]
    const float* __restrict__ edge_feats,   // [E,4,128]
    const int*   __restrict__ sender)       // [E]
{
    int n = blockIdx.x;
    int tid = threadIdx.x;
    int c = tid & 127;
    int par = tid >> 7;

    __shared__ float s_attr[32][16];
    __shared__ int   s_e[32];
    __shared__ int   s_send[32];
    __shared__ float s_part[16][128];

    float acc[16];
    #pragma unroll
    for (int i = 0; i < 16; i++) acc[i] = 0.0f;

    int beg = d_offsets[n];
    int end = d_offsets[n + 1];

    for (int base = beg; base < end; base += 32) {
        int m = end - base;
        if (m > 32) m = 32;
        if (tid < m) {
            int ee = d_sorted[base + tid];
            s_e[tid] = ee;
            s_send[tid] = sender[ee];
        }
        for (int i = tid; i < m * 16; i += 256) {
            int j = i >> 4;
            s_attr[j][i & 15] = edge_attrs[(size_t)d_sorted[base + j] * 16 + (i & 15)];
        }
        __syncthreads();

        int j = par;
        float e0 = 0.f, e1 = 0.f, e2 = 0.f, e3 = 0.f, hs = 0.f;
        if (j < m) {
            const float* efp = edge_feats + (size_t)s_e[j] * 512;
            e0 = efp[c]; e1 = efp[128 + c]; e2 = efp[256 + c]; e3 = efp[384 + c];
            hs = d_h[(size_t)s_send[j] * 128 + c];
        }
        while (j < m) {
            int jn = j + 2;
            float f0 = 0.f, f1 = 0.f, f2 = 0.f, f3 = 0.f, hn = 0.f;
            if (jn < m) {
                const float* efp = edge_feats + (size_t)s_e[jn] * 512;
                f0 = efp[c]; f1 = efp[128 + c]; f2 = efp[256 + c]; f3 = efp[384 + c];
                hn = d_h[(size_t)s_send[jn] * 128 + c];
            }
            const float* at = s_attr[j];
            float p0 = hs * e0, p1 = hs * e1, p2 = hs * e2, p3 = hs * e3;
            acc[0]  += p0 * at[0];
            acc[1]  += p1 * at[1];
            acc[2]  += p1 * at[2];
            acc[3]  += p1 * at[3];
            acc[4]  += p2 * at[4];
            acc[5]  += p2 * at[5];
            acc[6]  += p2 * at[6];
            acc[7]  += p2 * at[7];
            acc[8]  += p2 * at[8];
            acc[9]  += p3 * at[9];
            acc[10] += p3 * at[10];
            acc[11] += p3 * at[11];
            acc[12] += p3 * at[12];
            acc[13] += p3 * at[13];
            acc[14] += p3 * at[14];
            acc[15] += p3 * at[15];
            j = jn; e0 = f0; e1 = f1; e2 = f2; e3 = f3; hs = hn;
        }
        __syncthreads();
    }

    if (par) {
        #pragma unroll
        for (int lm = 0; lm < 16; lm++) s_part[lm][c] = acc[lm];
    }
    __syncthreads();
    if (!par) {
        size_t ob = (size_t)n * 2048 + c;
        #pragma unroll
        for (int lm = 0; lm < 16; lm++)
            d_msg[ob + (size_t)lm * 128] = acc[lm] + s_part[lm][c];
    }
}

// ---------------------------------------------------------------------------
// Output GEMM via mma.sync bf16 (HMMA), hi/lo compensated (hh + hl + lh).
// Persistent tile queue. Tile = 128 gathered msg rows x 128 cols x K=128.
// Smem: A_hi/A_lo/B_hi/B_lo, each 128 rows x 136 bf16 (padded, ldmatrix
// conflict-free). 8 warps: warp tile 32 rows x 64 cols (2 x m16, 8 x n8).
// ---------------------------------------------------------------------------
#define ROWP 136
#define BUF_BYTES (128 * ROWP * 2)          // 34816
#define DSMEM_BYTES (4 * BUF_BYTES)         // 139264

__global__ __launch_bounds__(256) void out_gemm_mma(float* __restrict__ out, int NE)
{
    extern __shared__ __nv_bfloat16 smb[];
    __nv_bfloat16* A_hi = smb;
    __nv_bfloat16* A_lo = smb + 128 * ROWP;
    __nv_bfloat16* B_hi = smb + 2 * 128 * ROWP;
    __nv_bfloat16* B_lo = smb + 3 * 128 * ROWP;

    __shared__ int s_off[128];
    __shared__ int s_toff[NG_MAX + 1];
    __shared__ int s_eoff[NE_MAX + 1];
    __shared__ int s_tile;

    int tid = threadIdx.x, wid = tid >> 5, lid = tid & 31;
    int NG = NE * 4;
    if (tid <= NG) s_toff[tid] = d_tile_off[tid];
    if (tid <= NE) s_eoff[tid] = d_elem_off[tid];
    __syncthreads();
    int ntiles = s_toff[NG];

    int wm0 = (wid & 3) * 32;     // warp row base
    int wn0 = (wid >> 2) * 64;    // warp col base

    // ldmatrix lane geometry (element offsets within a buffer)
    int a_row0 = wm0 + ((lid >> 3) & 1) * 8 + (lid & 7);
    int a_kadd = ((lid >> 4) & 1) * 8;
    uint32_t aoff[2];
    #pragma unroll
    for (int mt = 0; mt < 2; mt++)
        aoff[mt] = (uint32_t)(((a_row0 + mt * 16) * ROWP + a_kadd) * 2);
    int b_row0 = wn0 + ((lid >> 4) & 1) * 8 + (lid & 7);
    int b_kadd = ((lid >> 3) & 1) * 8;
    uint32_t boff[4];
    #pragma unroll
    for (int p = 0; p < 4; p++)
        boff[p] = (uint32_t)(((b_row0 + p * 16) * ROWP + b_kadd) * 2);

    uint32_t sA_hi = smem_u32(A_hi), sA_lo = smem_u32(A_lo);
    uint32_t sB_hi = smem_u32(B_hi), sB_lo = smem_u32(B_lo);

    // fill-phase geometry: row r, half hc (64 cols each)
    int fr = tid >> 1, fhc = tid & 1;
    int fbase = fr * ROWP + fhc * 64;

    while (true) {
        if (tid == 0) s_tile = atomicAdd(&d_tile_ctr, 1);
        __syncthreads();
        int t = s_tile;
        if (t >= ntiles) break;

        int g = 0;
        while (s_toff[g + 1] <= t) g++;
        int l = g & 3, e = g >> 2;
        int tw = 2 * l + 1;
        int cbeg = s_eoff[e];
        int rows = (s_eoff[e + 1] - cbeg) * tw;
        int tile = (t - s_toff[g]) * 128;

        if (tid < 128) {
            int rr = tile + tid;
            int off = -1;
            if (rr < rows) {
                int node = d_node_by_elem[cbeg + rr / tw];
                off = (node * 16 + l * l + rr % tw) * 128;
            }
            s_off[tid] = off;
        }
        __syncthreads();

        // --- fill A (gather + hi/lo split) ---
        {
            int off = s_off[fr];
            if (off >= 0) {
                const float* src = d_msg + (size_t)off + fhc * 64;
                #pragma unroll
                for (int q = 0; q < 8; q++) {
                    float4 v0 = *(const float4*)(src + q * 8);
                    float4 v1 = *(const float4*)(src + q * 8 + 4);
                    float xs[8] = {v0.x, v0.y, v0.z, v0.w, v1.x, v1.y, v1.z, v1.w};
                    uint32_t hw[4], lw[4];
                    #pragma unroll
                    for (int m2 = 0; m2 < 4; m2++) {
                        __nv_bfloat16 h0 = __float2bfloat16_rn(xs[2 * m2]);
                        __nv_bfloat16 h1 = __float2bfloat16_rn(xs[2 * m2 + 1]);
                        float l0 = xs[2 * m2] - __bfloat162float(h0);
                        float l1 = xs[2 * m2 + 1] - __bfloat162float(h1);
                        __nv_bfloat162 hp(h0, h1);
                        __nv_bfloat162 lp(__float2bfloat16_rn(l0), __float2bfloat16_rn(l1));
                        hw[m2] = *(uint32_t*)&hp;
                        lw[m2] = *(uint32_t*)&lp;
                    }
                    *(uint4*)&A_hi[fbase + q * 8] = make_uint4(hw[0], hw[1], hw[2], hw[3]);
                    *(uint4*)&A_lo[fbase + q * 8] = make_uint4(lw[0], lw[1], lw[2], lw[3]);
                }
            } else {
                #pragma unroll
                for (int q = 0; q < 8; q++) {
                    *(uint4*)&A_hi[fbase + q * 8] = make_uint4(0, 0, 0, 0);
                    *(uint4*)&A_lo[fbase + q * 8] = make_uint4(0, 0, 0, 0);
                }
            }
            // --- fill B (plain bf16 copy) ---
            const __nv_bfloat16* bh = d_WcT_hi + ((size_t)g * 128 + fr) * 128 + fhc * 64;
            const __nv_bfloat16* bl = d_WcT_lo + ((size_t)g * 128 + fr) * 128 + fhc * 64;
            #pragma unroll
            for (int q = 0; q < 8; q++) {
                *(uint4*)&B_hi[fbase + q * 8] = *(const uint4*)(bh + q * 8);
                *(uint4*)&B_lo[fbase + q * 8] = *(const uint4*)(bl + q * 8);
            }
        }
        __syncthreads();

        // --- compute ---
        float acc[2][8][4];
        #pragma unroll
        for (int mt = 0; mt < 2; mt++)
            #pragma unroll
            for (int nt = 0; nt < 8; nt++)
                #pragma unroll
                for (int q = 0; q < 4; q++) acc[mt][nt][q] = 0.0f;

        #pragma unroll
        for (int ks = 0; ks < 8; ks++) {
            uint32_t kb = (uint32_t)(ks * 16 * 2);
            uint32_t ah[2][4], al[2][4];
            #pragma unroll
            for (int mt = 0; mt < 2; mt++) {
                LDSM4(ah[mt][0], ah[mt][1], ah[mt][2], ah[mt][3], sA_hi + aoff[mt] + kb);
                LDSM4(al[mt][0], al[mt][1], al[mt][2], al[mt][3], sA_lo + aoff[mt] + kb);
            }
            uint32_t bh[8][2], bl[8][2];
            #pragma unroll
            for (int p = 0; p < 4; p++) {
                uint32_t r0, r1, r2, r3;
                LDSM4(r0, r1, r2, r3, sB_hi + boff[p] + kb);
                bh[2 * p][0] = r0; bh[2 * p][1] = r1;
                bh[2 * p + 1][0] = r2; bh[2 * p + 1][1] = r3;
                LDSM4(r0, r1, r2, r3, sB_lo + boff[p] + kb);
                bl[2 * p][0] = r0; bl[2 * p][1] = r1;
                bl[2 * p + 1][0] = r2; bl[2 * p + 1][1] = r3;
            }
            #pragma unroll
            for (int mt = 0; mt < 2; mt++)
                #pragma unroll
                for (int nt = 0; nt < 8; nt++) {
                    MMA16816(acc[mt][nt], ah[mt], bh[nt]);   // hi*hi
                    MMA16816(acc[mt][nt], ah[mt], bl[nt]);   // hi*lo
                    MMA16816(acc[mt][nt], al[mt], bh[nt]);   // lo*hi
                }
        }

        // --- epilogue: scatter to out via s_off ---
        #pragma unroll
        for (int mt = 0; mt < 2; mt++) {
            int r0 = wm0 + mt * 16 + (lid >> 2);
            int off0 = s_off[r0];
            int off1 = s_off[r0 + 8];
            #pragma unroll
            for (int nt = 0; nt < 8; nt++) {
                int col = wn0 + nt * 8 + (lid & 3) * 2;
                if (off0 >= 0)
                    *(float2*)&out[(size_t)off0 + col] =
                        make_float2(acc[mt][nt][0], acc[mt][nt][1]);
                if (off1 >= 0)
                    *(float2*)&out[(size_t)off1 + col] =
                        make_float2(acc[mt][nt][2], acc[mt][nt][3]);
            }
        }
        __syncthreads();   // protect smem/s_off/s_tile before next tile
    }
}

// ---------------------------------------------------------------------------
// Launch
// ---------------------------------------------------------------------------
extern "C" void kernel_launch(void* const* d_in, const int* in_sizes, int n_in,
                              void* d_out, int out_size)
{
    const float* node_feats = (const float*)d_in[0];   // [N,128]
    const float* edge_attrs = (const float*)d_in[1];   // [E,16]
    const float* edge_feats = (const float*)d_in[2];   // [E,512]
    const float* W_up       = (const float*)d_in[3];   // [128,128]
    const float* W_lin      = (const float*)d_in[4];   // [4,128,128]
    const float* W_skip     = (const float*)d_in[5];   // [NE,4,128,128]
    const int*   edge_index = (const int*)d_in[6];     // [2,E]
    const int*   node_elem  = (const int*)d_in[7];     // [N]

    int N  = in_sizes[7];
    int E  = in_sizes[1] / 16;
    int NE = in_sizes[5] / (4 * 128 * 128);

    const int* sender = edge_index;
    const int* recv   = edge_index + E;

    int gx = (N + 127) / 128;

    // immediate host-side attribute set (not stream-ordered; capture-safe)
    cudaFuncSetAttribute(out_gemm_mma,
                         cudaFuncAttributeMaxDynamicSharedMemorySize, DSMEM_BYTES);

    // 0. h GEMM + WcT bf16 hi/lo + receiver histogram (counts pre-zeroed:
    //    initial load zeros + scan re-zeroes each replay)
    gemm_fused_kernel<<<dim3(gx, 1, 1 + NE * 4), 256>>>(
        node_feats, W_up, W_lin, W_skip, recv, N, E, NE);
    if (gx < 2)   // degenerate: no helper blocks existed
        hist_kernel<<<(E + 255) / 256, 256>>>(recv, E);

    // 1. scan (+ re-zero counts) + element grouping + tile queue
    scan_elem_kernel<<<2, 1024>>>(node_elem, N, NE);

    // 2. counting-sort scatter
    scatter_kernel<<<(E + 255) / 256, 256>>>(recv, E);

    // 3. per-node edge accumulation -> msg
    edge_accum_kernel<<<N, 256>>>(edge_attrs, edge_feats, sender);

    // 4. output GEMM on tensor cores (mma.sync bf16, hi/lo compensated)
    out_gemm_mma<<<148, 256, DSMEM_BYTES>>>((float*)d_out, NE);
}

// round 9
// speedup vs baseline: 1.5120x; 1.1748x over previous
#include <cuda_runtime.h>
#include <cuda_bf16.h>
#include <cstdint>

// ---------------------------------------------------------------------------
// MACE invariant message passing:
//   h   = node_feats @ W_up
//   m   = h[sender] * edge_attrs * edge_feats[l_of_lm]   (per edge)
//   msg = segment_sum over receiver
//   out = msg @ ( W_lin[l] @ W_skip[elem,l] / 16 )       (grouped by element)
// Output GEMM: warp-level mma.sync bf16 (HMMA) with hi/lo compensation.
// ---------------------------------------------------------------------------

typedef unsigned long long u64;

#define N_MAX 6144
#define E_MAX 131072
#define NE_MAX 16
#define NG_MAX (NE_MAX * 4)
#define AST 68    // As row stride (floats) in the scalar GEMM (BM=64 + pad)

// Static device scratch (allocation-free per harness rules)
__device__ float d_h[(size_t)N_MAX * 128];
__device__ float d_msg[(size_t)N_MAX * 16 * 128];
__device__ __nv_bfloat16 d_WcT_hi[(size_t)NG_MAX * 128 * 128];
__device__ __nv_bfloat16 d_WcT_lo[(size_t)NG_MAX * 128 * 128];
__device__ int   d_sorted[E_MAX];
__device__ int   d_counts[N_MAX];          // zero-init; scan re-zeroes after use
__device__ int   d_offsets[N_MAX + 1];
__device__ int   d_cursor[N_MAX];
__device__ int   d_node_by_elem[N_MAX];
__device__ int   d_elem_off[NE_MAX + 1];
__device__ int   d_elem_cur[NE_MAX];
__device__ int   d_tile_off[NG_MAX + 1];
__device__ int   d_tile_ctr;

// --------------------------- helpers ---------------------------------------
__device__ __forceinline__ uint32_t smem_u32(const void* p) {
    uint32_t a;
    asm("{ .reg .u64 t; cvta.to.shared.u64 t, %1; cvt.u32.u64 %0, t; }"
        : "=r"(a) : "l"(p));
    return a;
}

#define LDSM4(r0, r1, r2, r3, addr) \
    asm volatile("ldmatrix.sync.aligned.m8n8.x4.shared.b16 {%0,%1,%2,%3}, [%4];" \
        : "=r"(r0), "=r"(r1), "=r"(r2), "=r"(r3) : "r"(addr))

#define MMA16816(c, a, b) \
    asm volatile("mma.sync.aligned.m16n8k16.row.col.f32.bf16.bf16.f32 " \
        "{%0,%1,%2,%3}, {%4,%5,%6,%7}, {%8,%9}, {%0,%1,%2,%3};" \
        : "+f"((c)[0]), "+f"((c)[1]), "+f"((c)[2]), "+f"((c)[3]) \
        : "r"((a)[0]), "r"((a)[1]), "r"((a)[2]), "r"((a)[3]), \
          "r"((b)[0]), "r"((b)[1]))

// ---------------------------------------------------------------------------
// Fused GEMM kernel (scalar fp32, BM=64, BN=128, BK=16, acc 4x8 -> no spills):
//   z == 0          : h = node_feats @ W_up          (tiles over blockIdx.x)
//   z >= 1, x <= 1  : WcT[g] rows x*64..+63 = transpose(W_lin[l] @ W_skip[g]/16)
//   z >= 1, x >= 2  : helper blocks run the receiver histogram
// ---------------------------------------------------------------------------
__global__ __launch_bounds__(256) void gemm_fused_kernel(
    const float* __restrict__ node_feats,
    const float* __restrict__ W_up,
    const float* __restrict__ W_lin,
    const float* __restrict__ W_skip,
    const int*   __restrict__ recv,
    int N, int E, int NE)
{
    const float* A;
    const float* B;
    int M;
    float scale;
    int z = blockIdx.z;
    int g = z - 1;
    int row0;

    if (z == 0) {
        A = node_feats; B = W_up; M = N; scale = 1.0f;
        row0 = blockIdx.x * 64;
    } else {
        if (blockIdx.x >= 2) {
            int nb  = gridDim.x - 2;
            int id  = (z - 1) * nb + (blockIdx.x - 2);
            int tot = (int)(gridDim.z - 1) * nb;
            for (int i = id * 256 + threadIdx.x; i < E; i += tot * 256)
                atomicAdd(&d_counts[recv[i]], 1);
            return;
        }
        int l = g & 3;
        A = W_lin  + (size_t)l * 16384;
        B = W_skip + (size_t)g * 16384;
        M = 128; scale = 1.0f / 16.0f;
        row0 = blockIdx.x * 64;
    }

    __shared__ float As[16 * AST];
    __shared__ float Bs[16 * 128];

    int tid = threadIdx.x;
    int ty = tid >> 4;      // 0..15 -> 4-row group
    int tx = tid & 15;      // 0..15 -> 4-col group (x2 halves)

    float acc[4][8];
    #pragma unroll
    for (int i = 0; i < 4; i++)
        #pragma unroll
        for (int j = 0; j < 8; j++) acc[i][j] = 0.0f;

    for (int kc = 0; kc < 128; kc += 16) {
        #pragma unroll
        for (int i = 0; i < 4; i++) {
            int idx = tid + i * 256;
            int r = idx >> 4, kk = idx & 15;
            int row = row0 + r;
            As[kk * AST + r] = (row < M) ? A[(size_t)row * 128 + kc + kk] : 0.0f;
        }
        #pragma unroll
        for (int i = 0; i < 8; i++) {
            int idx = tid + i * 256;
            int kk = idx >> 7, d = idx & 127;
            Bs[kk * 128 + d] = B[(size_t)(kc + kk) * 128 + d];
        }
        __syncthreads();
        #pragma unroll
        for (int kk = 0; kk < 16; kk++) {
            float4 a0 = *(const float4*)&As[kk * AST + ty * 4];
            float4 b0 = *(const float4*)&Bs[kk * 128 + tx * 4];
            float4 b1 = *(const float4*)&Bs[kk * 128 + 64 + tx * 4];
            float av[4] = {a0.x, a0.y, a0.z, a0.w};
            float bv[8] = {b0.x, b0.y, b0.z, b0.w, b1.x, b1.y, b1.z, b1.w};
            #pragma unroll
            for (int i = 0; i < 4; i++)
                #pragma unroll
                for (int j = 0; j < 8; j++) acc[i][j] += av[i] * bv[j];
        }
        __syncthreads();
    }

    if (z == 0) {
        #pragma unroll
        for (int i = 0; i < 4; i++) {
            int row = row0 + ty * 4 + i;
            if (row < M) {
                *(float4*)&d_h[(size_t)row * 128 + tx * 4] =
                    make_float4(acc[i][0], acc[i][1], acc[i][2], acc[i][3]);
                *(float4*)&d_h[(size_t)row * 128 + 64 + tx * 4] =
                    make_float4(acc[i][4], acc[i][5], acc[i][6], acc[i][7]);
            }
        }
    } else {
        // transposed bf16 hi/lo write: WcT[g][d][c], c = Wc row, d = Wc col
        #pragma unroll
        for (int i = 0; i < 4; i++) {
            int c = row0 + ty * 4 + i;
            #pragma unroll
            for (int j = 0; j < 8; j++) {
                int d = (j < 4) ? (tx * 4 + j) : (64 + tx * 4 + (j - 4));
                float v = acc[i][j] * scale;
                __nv_bfloat16 hv = __float2bfloat16_rn(v);
                float lv = v - __bfloat162float(hv);
                size_t o = ((size_t)g * 128 + d) * 128 + c;
                d_WcT_hi[o] = hv;
                d_WcT_lo[o] = __float2bfloat16_rn(lv);
            }
        }
    }
}

// Fallback hist (only if the fused grid had no helper blocks)
__global__ void hist_kernel(const int* __restrict__ recv, int E) {
    int i = blockIdx.x * blockDim.x + threadIdx.x;
    if (i < E) atomicAdd(&d_counts[recv[i]], 1);
}

// ---------------------------------------------------------------------------
// block 0: warp-shuffle scan of d_counts -> d_offsets / d_cursor, then
//          RE-ZEROES d_counts (keeps the zero invariant across graph replays)
// block 1: group nodes by element; tile prefix; reset tile counter
// ---------------------------------------------------------------------------
__global__ void scan_elem_kernel(const int* __restrict__ node_elem, int N, int NE) {
    int tid = threadIdx.x;

    if (blockIdx.x == 1) {
        __shared__ int scnt[NE_MAX];
        if (tid < NE) scnt[tid] = 0;
        __syncthreads();
        for (int i = tid; i < N; i += blockDim.x) atomicAdd(&scnt[node_elem[i]], 1);
        __syncthreads();
        if (tid == 0) {
            int run = 0;
            for (int e = 0; e < NE; e++) { d_elem_off[e] = run; d_elem_cur[e] = run; run += scnt[e]; }
            d_elem_off[NE] = run;
            int tp = 0;
            for (int g = 0; g < NE * 4; g++) {
                int l = g & 3;
                int rows = scnt[g >> 2] * (2 * l + 1);
                d_tile_off[g] = tp;
                tp += (rows + 127) >> 7;
            }
            d_tile_off[NE * 4] = tp;
            d_tile_ctr = 0;
        }
        __syncthreads();
        for (int i = tid; i < N; i += blockDim.x) {
            int pos = atomicAdd(&d_elem_cur[node_elem[i]], 1);
            d_node_by_elem[pos] = i;
        }
        return;
    }

    // block 0: scan (1024 threads x 6 elems = 6144 >= N_MAX)
    __shared__ int wtot[32];
    const int PER = 6;
    int lane = tid & 31, w = tid >> 5;
    int base = tid * PER;
    int cnt[PER];
    int run = 0;
    #pragma unroll
    for (int i = 0; i < PER; i++) {
        cnt[i] = (base + i < N) ? d_counts[base + i] : 0;
        run += cnt[i];
    }
    int ws = run;
    #pragma unroll
    for (int o = 1; o < 32; o <<= 1) {
        int t = __shfl_up_sync(0xffffffffu, ws, o);
        if (lane >= o) ws += t;
    }
    if (lane == 31) wtot[w] = ws;
    __syncthreads();
    if (w == 0) {
        int v = wtot[lane];
        #pragma unroll
        for (int o = 1; o < 32; o <<= 1) {
            int t = __shfl_up_sync(0xffffffffu, v, o);
            if (lane >= o) v += t;
        }
        wtot[lane] = v;
    }
    __syncthreads();
    int acc = (w ? wtot[w - 1] : 0) + (ws - run);
    if (tid == 0) d_offsets[0] = 0;
    #pragma unroll
    for (int i = 0; i < PER; i++) {
        int idx = base + i;
        if (idx < N) {
            d_cursor[idx] = acc;
            acc += cnt[i];
            d_offsets[idx + 1] = acc;
            d_counts[idx] = 0;     // restore zero invariant for next replay
        }
    }
}

__global__ void scatter_kernel(const int* __restrict__ recv, int E) {
    int i = blockIdx.x * blockDim.x + threadIdx.x;
    if (i < E) {
        int pos = atomicAdd(&d_cursor[recv[i]], 1);
        d_sorted[pos] = i;
    }
}

// ---------------------------------------------------------------------------
// Edge accumulation: one CTA per node, 256 threads.
// Thread = (channel c = tid&127, parity par = tid>>7), 16 lm accs per thread.
// Parities process alternating edges with depth-2 software pipeline (10 LDGs
// in flight), combined via smem. edge_feats read with streaming hint.
// l_of_lm: [0, 1,1,1, 2,2,2,2,2, 3,3,3,3,3,3,3]
// ---------------------------------------------------------------------------
__global__ __launch_bounds__(256) void edge_accum_kernel(
    const float* __restrict__ edge_attrs,   // [E,16]
    const float* __restrict__ edge_feats,   // [E,4,128]
    const int*   __restrict__ sender)       // [E]
{
    int n = blockIdx.x;
    int tid = threadIdx.x;
    int c = tid & 127;
    int par = tid >> 7;

    __shared__ float s_attr[32][16];
    __shared__ int   s_e[32];
    __shared__ int   s_send[32];
    __shared__ float s_part[16][128];

    float acc[16];
    #pragma unroll
    for (int i = 0; i < 16; i++) acc[i] = 0.0f;

    int beg = d_offsets[n];
    int end = d_offsets[n + 1];

    for (int base = beg; base < end; base += 32) {
        int m = end - base;
        if (m > 32) m = 32;
        if (tid < m) {
            int ee = d_sorted[base + tid];
            s_e[tid] = ee;
            s_send[tid] = sender[ee];
        }
        for (int i = tid; i < m * 16; i += 256) {
            int j = i >> 4;
            s_attr[j][i & 15] = __ldcs(&edge_attrs[(size_t)d_sorted[base + j] * 16 + (i & 15)]);
        }
        __syncthreads();

        // depth-2 software pipeline over this parity's edges (stride 2)
        int j = par;
        float A0[5] = {0.f, 0.f, 0.f, 0.f, 0.f};
        float A1[5] = {0.f, 0.f, 0.f, 0.f, 0.f};
        if (j < m) {
            const float* efp = edge_feats + (size_t)s_e[j] * 512;
            A0[0] = __ldcs(efp + c);       A0[1] = __ldcs(efp + 128 + c);
            A0[2] = __ldcs(efp + 256 + c); A0[3] = __ldcs(efp + 384 + c);
            A0[4] = d_h[(size_t)s_send[j] * 128 + c];
        }
        if (j + 2 < m) {
            const float* efp = edge_feats + (size_t)s_e[j + 2] * 512;
            A1[0] = __ldcs(efp + c);       A1[1] = __ldcs(efp + 128 + c);
            A1[2] = __ldcs(efp + 256 + c); A1[3] = __ldcs(efp + 384 + c);
            A1[4] = d_h[(size_t)s_send[j + 2] * 128 + c];
        }
        while (j < m) {
            float A2[5] = {0.f, 0.f, 0.f, 0.f, 0.f};
            if (j + 4 < m) {
                const float* efp = edge_feats + (size_t)s_e[j + 4] * 512;
                A2[0] = __ldcs(efp + c);       A2[1] = __ldcs(efp + 128 + c);
                A2[2] = __ldcs(efp + 256 + c); A2[3] = __ldcs(efp + 384 + c);
                A2[4] = d_h[(size_t)s_send[j + 4] * 128 + c];
            }
            const float* at = s_attr[j];
            float hs = A0[4];
            float p0 = hs * A0[0], p1 = hs * A0[1], p2 = hs * A0[2], p3 = hs * A0[3];
            acc[0]  += p0 * at[0];
            acc[1]  += p1 * at[1];
            acc[2]  += p1 * at[2];
            acc[3]  += p1 * at[3];
            acc[4]  += p2 * at[4];
            acc[5]  += p2 * at[5];
            acc[6]  += p2 * at[6];
            acc[7]  += p2 * at[7];
            acc[8]  += p2 * at[8];
            acc[9]  += p3 * at[9];
            acc[10] += p3 * at[10];
            acc[11] += p3 * at[11];
            acc[12] += p3 * at[12];
            acc[13] += p3 * at[13];
            acc[14] += p3 * at[14];
            acc[15] += p3 * at[15];
            #pragma unroll
            for (int q = 0; q < 5; q++) { A0[q] = A1[q]; A1[q] = A2[q]; }
            j += 2;
        }
        __syncthreads();
    }

    if (par) {
        #pragma unroll
        for (int lm = 0; lm < 16; lm++) s_part[lm][c] = acc[lm];
    }
    __syncthreads();
    if (!par) {
        size_t ob = (size_t)n * 2048 + c;
        #pragma unroll
        for (int lm = 0; lm < 16; lm++)
            d_msg[ob + (size_t)lm * 128] = acc[lm] + s_part[lm][c];
    }
}

// ---------------------------------------------------------------------------
// Output GEMM via mma.sync bf16 (HMMA), hi/lo compensated (hh + hl + lh).
// Persistent tile queue. Tile = 128 gathered msg rows x 128 cols x K=128.
// Smem: A_hi/A_lo/B_hi/B_lo, each 128 rows x 136 bf16 (padded, ldmatrix
// conflict-free). 8 warps: warp tile 32 rows x 64 cols (2 x m16, 8 x n8).
// B refill skipped when the group repeats (queue is group-ordered).
// ---------------------------------------------------------------------------
#define ROWP 136
#define BUF_BYTES (128 * ROWP * 2)          // 34816
#define DSMEM_BYTES (4 * BUF_BYTES)         // 139264

__global__ __launch_bounds__(256) void out_gemm_mma(float* __restrict__ out, int NE)
{
    extern __shared__ __nv_bfloat16 smb[];
    __nv_bfloat16* A_hi = smb;
    __nv_bfloat16* A_lo = smb + 128 * ROWP;
    __nv_bfloat16* B_hi = smb + 2 * 128 * ROWP;
    __nv_bfloat16* B_lo = smb + 3 * 128 * ROWP;

    __shared__ int s_off[128];
    __shared__ int s_toff[NG_MAX + 1];
    __shared__ int s_eoff[NE_MAX + 1];
    __shared__ int s_tile;

    int tid = threadIdx.x, wid = tid >> 5, lid = tid & 31;
    int NG = NE * 4;
    if (tid <= NG) s_toff[tid] = d_tile_off[tid];
    if (tid <= NE) s_eoff[tid] = d_elem_off[tid];
    __syncthreads();
    int ntiles = s_toff[NG];

    int wm0 = (wid & 3) * 32;     // warp row base
    int wn0 = (wid >> 2) * 64;    // warp col base

    // ldmatrix lane geometry (element offsets within a buffer)
    int a_row0 = wm0 + ((lid >> 3) & 1) * 8 + (lid & 7);
    int a_kadd = ((lid >> 4) & 1) * 8;
    uint32_t aoff[2];
    #pragma unroll
    for (int mt = 0; mt < 2; mt++)
        aoff[mt] = (uint32_t)(((a_row0 + mt * 16) * ROWP + a_kadd) * 2);
    int b_row0 = wn0 + ((lid >> 4) & 1) * 8 + (lid & 7);
    int b_kadd = ((lid >> 3) & 1) * 8;
    uint32_t boff[4];
    #pragma unroll
    for (int p = 0; p < 4; p++)
        boff[p] = (uint32_t)(((b_row0 + p * 16) * ROWP + b_kadd) * 2);

    uint32_t sA_hi = smem_u32(A_hi), sA_lo = smem_u32(A_lo);
    uint32_t sB_hi = smem_u32(B_hi), sB_lo = smem_u32(B_lo);

    // fill-phase geometry: row r, half hc (64 cols each)
    int fr = tid >> 1, fhc = tid & 1;
    int fbase = fr * ROWP + fhc * 64;

    int g_prev = -1;

    while (true) {
        if (tid == 0) s_tile = atomicAdd(&d_tile_ctr, 1);
        __syncthreads();
        int t = s_tile;
        if (t >= ntiles) break;

        int g = 0;
        while (s_toff[g + 1] <= t) g++;
        int l = g & 3, e = g >> 2;
        int tw = 2 * l + 1;
        int cbeg = s_eoff[e];
        int rows = (s_eoff[e + 1] - cbeg) * tw;
        int tile = (t - s_toff[g]) * 128;
        bool fillB = (g != g_prev);
        g_prev = g;

        if (tid < 128) {
            int rr = tile + tid;
            int off = -1;
            if (rr < rows) {
                int node = d_node_by_elem[cbeg + rr / tw];
                off = (node * 16 + l * l + rr % tw) * 128;
            }
            s_off[tid] = off;
        }
        __syncthreads();

        // --- fill A (gather + hi/lo split) ---
        {
            int off = s_off[fr];
            if (off >= 0) {
                const float* src = d_msg + (size_t)off + fhc * 64;
                #pragma unroll
                for (int q = 0; q < 8; q++) {
                    float4 v0 = *(const float4*)(src + q * 8);
                    float4 v1 = *(const float4*)(src + q * 8 + 4);
                    float xs[8] = {v0.x, v0.y, v0.z, v0.w, v1.x, v1.y, v1.z, v1.w};
                    uint32_t hw[4], lw[4];
                    #pragma unroll
                    for (int m2 = 0; m2 < 4; m2++) {
                        __nv_bfloat16 h0 = __float2bfloat16_rn(xs[2 * m2]);
                        __nv_bfloat16 h1 = __float2bfloat16_rn(xs[2 * m2 + 1]);
                        float l0 = xs[2 * m2] - __bfloat162float(h0);
                        float l1 = xs[2 * m2 + 1] - __bfloat162float(h1);
                        __nv_bfloat162 hp(h0, h1);
                        __nv_bfloat162 lp(__float2bfloat16_rn(l0), __float2bfloat16_rn(l1));
                        hw[m2] = *(uint32_t*)&hp;
                        lw[m2] = *(uint32_t*)&lp;
                    }
                    *(uint4*)&A_hi[fbase + q * 8] = make_uint4(hw[0], hw[1], hw[2], hw[3]);
                    *(uint4*)&A_lo[fbase + q * 8] = make_uint4(lw[0], lw[1], lw[2], lw[3]);
                }
            } else {
                #pragma unroll
                for (int q = 0; q < 8; q++) {
                    *(uint4*)&A_hi[fbase + q * 8] = make_uint4(0, 0, 0, 0);
                    *(uint4*)&A_lo[fbase + q * 8] = make_uint4(0, 0, 0, 0);
                }
            }
            // --- fill B (plain bf16 copy) only when the group changed ---
            if (fillB) {
                const __nv_bfloat16* bh = d_WcT_hi + ((size_t)g * 128 + fr) * 128 + fhc * 64;
                const __nv_bfloat16* bl = d_WcT_lo + ((size_t)g * 128 + fr) * 128 + fhc * 64;
                #pragma unroll
                for (int q = 0; q < 8; q++) {
                    *(uint4*)&B_hi[fbase + q * 8] = *(const uint4*)(bh + q * 8);
                    *(uint4*)&B_lo[fbase + q * 8] = *(const uint4*)(bl + q * 8);
                }
            }
        }
        __syncthreads();

        // --- compute ---
        float acc[2][8][4];
        #pragma unroll
        for (int mt = 0; mt < 2; mt++)
            #pragma unroll
            for (int nt = 0; nt < 8; nt++)
                #pragma unroll
                for (int q = 0; q < 4; q++) acc[mt][nt][q] = 0.0f;

        #pragma unroll
        for (int ks = 0; ks < 8; ks++) {
            uint32_t kb = (uint32_t)(ks * 16 * 2);
            uint32_t ah[2][4], al[2][4];
            #pragma unroll
            for (int mt = 0; mt < 2; mt++) {
                LDSM4(ah[mt][0], ah[mt][1], ah[mt][2], ah[mt][3], sA_hi + aoff[mt] + kb);
                LDSM4(al[mt][0], al[mt][1], al[mt][2], al[mt][3], sA_lo + aoff[mt] + kb);
            }
            uint32_t bh[8][2], bl[8][2];
            #pragma unroll
            for (int p = 0; p < 4; p++) {
                uint32_t r0, r1, r2, r3;
                LDSM4(r0, r1, r2, r3, sB_hi + boff[p] + kb);
                bh[2 * p][0] = r0; bh[2 * p][1] = r1;
                bh[2 * p + 1][0] = r2; bh[2 * p + 1][1] = r3;
                LDSM4(r0, r1, r2, r3, sB_lo + boff[p] + kb);
                bl[2 * p][0] = r0; bl[2 * p][1] = r1;
                bl[2 * p + 1][0] = r2; bl[2 * p + 1][1] = r3;
            }
            #pragma unroll
            for (int mt = 0; mt < 2; mt++)
                #pragma unroll
                for (int nt = 0; nt < 8; nt++) {
                    MMA16816(acc[mt][nt], ah[mt], bh[nt]);   // hi*hi
                    MMA16816(acc[mt][nt], ah[mt], bl[nt]);   // hi*lo
                    MMA16816(acc[mt][nt], al[mt], bh[nt]);   // lo*hi
                }
        }

        // --- epilogue: scatter to out via s_off ---
        #pragma unroll
        for (int mt = 0; mt < 2; mt++) {
            int r0 = wm0 + mt * 16 + (lid >> 2);
            int off0 = s_off[r0];
            int off1 = s_off[r0 + 8];
            #pragma unroll
            for (int nt = 0; nt < 8; nt++) {
                int col = wn0 + nt * 8 + (lid & 3) * 2;
                if (off0 >= 0)
                    *(float2*)&out[(size_t)off0 + col] =
                        make_float2(acc[mt][nt][0], acc[mt][nt][1]);
                if (off1 >= 0)
                    *(float2*)&out[(size_t)off1 + col] =
                        make_float2(acc[mt][nt][2], acc[mt][nt][3]);
            }
        }
        __syncthreads();   // protect smem/s_off/s_tile before next tile
    }
}

// ---------------------------------------------------------------------------
// Launch
// ---------------------------------------------------------------------------
extern "C" void kernel_launch(void* const* d_in, const int* in_sizes, int n_in,
                              void* d_out, int out_size)
{
    const float* node_feats = (const float*)d_in[0];   // [N,128]
    const float* edge_attrs = (const float*)d_in[1];   // [E,16]
    const float* edge_feats = (const float*)d_in[2];   // [E,512]
    const float* W_up       = (const float*)d_in[3];   // [128,128]
    const float* W_lin      = (const float*)d_in[4];   // [4,128,128]
    const float* W_skip     = (const float*)d_in[5];   // [NE,4,128,128]
    const int*   edge_index = (const int*)d_in[6];     // [2,E]
    const int*   node_elem  = (const int*)d_in[7];     // [N]

    int N  = in_sizes[7];
    int E  = in_sizes[1] / 16;
    int NE = in_sizes[5] / (4 * 128 * 128);

    const int* sender = edge_index;
    const int* recv   = edge_index + E;

    int gx = (N + 63) / 64;

    // immediate host-side attribute set (not stream-ordered; capture-safe)
    cudaFuncSetAttribute(out_gemm_mma,
                         cudaFuncAttributeMaxDynamicSharedMemorySize, DSMEM_BYTES);

    // 0. h GEMM + WcT bf16 hi/lo + receiver histogram (counts pre-zeroed:
    //    initial load zeros + scan re-zeroes each replay)
    gemm_fused_kernel<<<dim3(gx, 1, 1 + NE * 4), 256>>>(
        node_feats, W_up, W_lin, W_skip, recv, N, E, NE);
    if (gx < 3)   // degenerate: no helper blocks existed
        hist_kernel<<<(E + 255) / 256, 256>>>(recv, E);

    // 1. scan (+ re-zero counts) + element grouping + tile queue
    scan_elem_kernel<<<2, 1024>>>(node_elem, N, NE);

    // 2. counting-sort scatter
    scatter_kernel<<<(E + 255) / 256, 256>>>(recv, E);

    // 3. per-node edge accumulation -> msg
    edge_accum_kernel<<<N, 256>>>(edge_attrs, edge_feats, sender);

    // 4. output GEMM on tensor cores (mma.sync bf16, hi/lo compensated)
    out_gemm_mma<<<148, 256, DSMEM_BYTES>>>((float*)d_out, NE);
}

// round 10
// speedup vs baseline: 1.5298x; 1.0118x over previous
#include <cuda_runtime.h>
#include <cuda_bf16.h>
#include <cstdint>

// ---------------------------------------------------------------------------
// MACE invariant message passing:
//   h   = node_feats @ W_up
//   m   = h[sender] * edge_attrs * edge_feats[l_of_lm]   (per edge)
//   msg = segment_sum over receiver  (stored as bf16 hi/lo)
//   out = msg @ ( W_lin[l] @ W_skip[elem,l] / 16 )       (grouped by element)
// Output GEMM: warp-level mma.sync bf16 (HMMA) with hi/lo compensation.
// ---------------------------------------------------------------------------

typedef unsigned long long u64;

#define N_MAX 6144
#define E_MAX 131072
#define NE_MAX 16
#define NG_MAX (NE_MAX * 4)
#define AST 68    // As row stride (floats) in the scalar GEMM (BM=64 + pad)

// Static device scratch (allocation-free per harness rules)
__device__ float d_h[(size_t)N_MAX * 128];
__device__ __nv_bfloat16 d_msg_hi[(size_t)N_MAX * 16 * 128];
__device__ __nv_bfloat16 d_msg_lo[(size_t)N_MAX * 16 * 128];
__device__ __nv_bfloat16 d_WcT_hi[(size_t)NG_MAX * 128 * 128];
__device__ __nv_bfloat16 d_WcT_lo[(size_t)NG_MAX * 128 * 128];
__device__ int   d_sorted[E_MAX];
__device__ int   d_counts[N_MAX];          // zero-init; scan re-zeroes after use
__device__ int   d_offsets[N_MAX + 1];
__device__ int   d_cursor[N_MAX];
__device__ int   d_node_by_elem[N_MAX];
__device__ int   d_elem_off[NE_MAX + 1];
__device__ int   d_elem_cur[NE_MAX];
__device__ int   d_tile_off[NG_MAX + 1];
__device__ int   d_tile_ctr;

// --------------------------- helpers ---------------------------------------
__device__ __forceinline__ uint32_t smem_u32(const void* p) {
    uint32_t a;
    asm("{ .reg .u64 t; cvta.to.shared.u64 t, %1; cvt.u32.u64 %0, t; }"
        : "=r"(a) : "l"(p));
    return a;
}

#define CP16(dst, src) \
    asm volatile("cp.async.cg.shared.global [%0], [%1], 16;" \
        :: "r"(dst), "l"(src) : "memory")
#define CP_COMMIT() asm volatile("cp.async.commit_group;" ::: "memory")
template <int W>
__device__ __forceinline__ void cp_wait() {
    asm volatile("cp.async.wait_group %0;" :: "n"(W) : "memory");
}

#define LDSM4(r0, r1, r2, r3, addr) \
    asm volatile("ldmatrix.sync.aligned.m8n8.x4.shared.b16 {%0,%1,%2,%3}, [%4];" \
        : "=r"(r0), "=r"(r1), "=r"(r2), "=r"(r3) : "r"(addr))

#define MMA16816(c, a, b) \
    asm volatile("mma.sync.aligned.m16n8k16.row.col.f32.bf16.bf16.f32 " \
        "{%0,%1,%2,%3}, {%4,%5,%6,%7}, {%8,%9}, {%0,%1,%2,%3};" \
        : "+f"((c)[0]), "+f"((c)[1]), "+f"((c)[2]), "+f"((c)[3]) \
        : "r"((a)[0]), "r"((a)[1]), "r"((a)[2]), "r"((a)[3]), \
          "r"((b)[0]), "r"((b)[1]))

// ---------------------------------------------------------------------------
// Fused GEMM kernel (scalar fp32, BM=64, BN=128, BK=16, acc 4x8 -> no spills):
//   z == 0          : h = node_feats @ W_up          (tiles over blockIdx.x)
//   z >= 1, x <= 1  : WcT[g] rows x*64..+63 = transpose(W_lin[l] @ W_skip[g]/16)
//   z >= 1, x >= 2  : helper blocks run the receiver histogram
// ---------------------------------------------------------------------------
__global__ __launch_bounds__(256) void gemm_fused_kernel(
    const float* __restrict__ node_feats,
    const float* __restrict__ W_up,
    const float* __restrict__ W_lin,
    const float* __restrict__ W_skip,
    const int*   __restrict__ recv,
    int N, int E, int NE)
{
    const float* A;
    const float* B;
    int M;
    float scale;
    int z = blockIdx.z;
    int g = z - 1;
    int row0;

    if (z == 0) {
        A = node_feats; B = W_up; M = N; scale = 1.0f;
        row0 = blockIdx.x * 64;
    } else {
        if (blockIdx.x >= 2) {
            int nb  = gridDim.x - 2;
            int id  = (z - 1) * nb + (blockIdx.x - 2);
            int tot = (int)(gridDim.z - 1) * nb;
            for (int i = id * 256 + threadIdx.x; i < E; i += tot * 256)
                atomicAdd(&d_counts[recv[i]], 1);
            return;
        }
        int l = g & 3;
        A = W_lin  + (size_t)l * 16384;
        B = W_skip + (size_t)g * 16384;
        M = 128; scale = 1.0f / 16.0f;
        row0 = blockIdx.x * 64;
    }

    __shared__ float As[16 * AST];
    __shared__ float Bs[16 * 128];

    int tid = threadIdx.x;
    int ty = tid >> 4;      // 0..15 -> 4-row group
    int tx = tid & 15;      // 0..15 -> 4-col group (x2 halves)

    float acc[4][8];
    #pragma unroll
    for (int i = 0; i < 4; i++)
        #pragma unroll
        for (int j = 0; j < 8; j++) acc[i][j] = 0.0f;

    for (int kc = 0; kc < 128; kc += 16) {
        #pragma unroll
        for (int i = 0; i < 4; i++) {
            int idx = tid + i * 256;
            int r = idx >> 4, kk = idx & 15;
            int row = row0 + r;
            As[kk * AST + r] = (row < M) ? A[(size_t)row * 128 + kc + kk] : 0.0f;
        }
        #pragma unroll
        for (int i = 0; i < 8; i++) {
            int idx = tid + i * 256;
            int kk = idx >> 7, d = idx & 127;
            Bs[kk * 128 + d] = B[(size_t)(kc + kk) * 128 + d];
        }
        __syncthreads();
        #pragma unroll
        for (int kk = 0; kk < 16; kk++) {
            float4 a0 = *(const float4*)&As[kk * AST + ty * 4];
            float4 b0 = *(const float4*)&Bs[kk * 128 + tx * 4];
            float4 b1 = *(const float4*)&Bs[kk * 128 + 64 + tx * 4];
            float av[4] = {a0.x, a0.y, a0.z, a0.w};
            float bv[8] = {b0.x, b0.y, b0.z, b0.w, b1.x, b1.y, b1.z, b1.w};
            #pragma unroll
            for (int i = 0; i < 4; i++)
                #pragma unroll
                for (int j = 0; j < 8; j++) acc[i][j] += av[i] * bv[j];
        }
        __syncthreads();
    }

    if (z == 0) {
        #pragma unroll
        for (int i = 0; i < 4; i++) {
            int row = row0 + ty * 4 + i;
            if (row < M) {
                *(float4*)&d_h[(size_t)row * 128 + tx * 4] =
                    make_float4(acc[i][0], acc[i][1], acc[i][2], acc[i][3]);
                *(float4*)&d_h[(size_t)row * 128 + 64 + tx * 4] =
                    make_float4(acc[i][4], acc[i][5], acc[i][6], acc[i][7]);
            }
        }
    } else {
        // transposed bf16 hi/lo write: WcT[g][d][c], c = Wc row, d = Wc col
        #pragma unroll
        for (int i = 0; i < 4; i++) {
            int c = row0 + ty * 4 + i;
            #pragma unroll
            for (int j = 0; j < 8; j++) {
                int d = (j < 4) ? (tx * 4 + j) : (64 + tx * 4 + (j - 4));
                float v = acc[i][j] * scale;
                __nv_bfloat16 hv = __float2bfloat16_rn(v);
                float lv = v - __bfloat162float(hv);
                size_t o = ((size_t)g * 128 + d) * 128 + c;
                d_WcT_hi[o] = hv;
                d_WcT_lo[o] = __float2bfloat16_rn(lv);
            }
        }
    }
}

// Fallback hist (only if the fused grid had no helper blocks)
__global__ void hist_kernel(const int* __restrict__ recv, int E) {
    int i = blockIdx.x * blockDim.x + threadIdx.x;
    if (i < E) atomicAdd(&d_counts[recv[i]], 1);
}

// ---------------------------------------------------------------------------
// block 0: warp-shuffle scan of d_counts -> d_offsets / d_cursor, then
//          RE-ZEROES d_counts (keeps the zero invariant across graph replays)
// block 1: group nodes by element; tile prefix; reset tile counter
// ---------------------------------------------------------------------------
__global__ void scan_elem_kernel(const int* __restrict__ node_elem, int N, int NE) {
    int tid = threadIdx.x;

    if (blockIdx.x == 1) {
        __shared__ int scnt[NE_MAX];
        if (tid < NE) scnt[tid] = 0;
        __syncthreads();
        for (int i = tid; i < N; i += blockDim.x) atomicAdd(&scnt[node_elem[i]], 1);
        __syncthreads();
        if (tid == 0) {
            int run = 0;
            for (int e = 0; e < NE; e++) { d_elem_off[e] = run; d_elem_cur[e] = run; run += scnt[e]; }
            d_elem_off[NE] = run;
            int tp = 0;
            for (int g = 0; g < NE * 4; g++) {
                int l = g & 3;
                int rows = scnt[g >> 2] * (2 * l + 1);
                d_tile_off[g] = tp;
                tp += (rows + 127) >> 7;
            }
            d_tile_off[NE * 4] = tp;
            d_tile_ctr = 0;
        }
        __syncthreads();
        for (int i = tid; i < N; i += blockDim.x) {
            int pos = atomicAdd(&d_elem_cur[node_elem[i]], 1);
            d_node_by_elem[pos] = i;
        }
        return;
    }

    // block 0: scan (1024 threads x 6 elems = 6144 >= N_MAX)
    __shared__ int wtot[32];
    const int PER = 6;
    int lane = tid & 31, w = tid >> 5;
    int base = tid * PER;
    int cnt[PER];
    int run = 0;
    #pragma unroll
    for (int i = 0; i < PER; i++) {
        cnt[i] = (base + i < N) ? d_counts[base + i] : 0;
        run += cnt[i];
    }
    int ws = run;
    #pragma unroll
    for (int o = 1; o < 32; o <<= 1) {
        int t = __shfl_up_sync(0xffffffffu, ws, o);
        if (lane >= o) ws += t;
    }
    if (lane == 31) wtot[w] = ws;
    __syncthreads();
    if (w == 0) {
        int v = wtot[lane];
        #pragma unroll
        for (int o = 1; o < 32; o <<= 1) {
            int t = __shfl_up_sync(0xffffffffu, v, o);
            if (lane >= o) v += t;
        }
        wtot[lane] = v;
    }
    __syncthreads();
    int acc = (w ? wtot[w - 1] : 0) + (ws - run);
    if (tid == 0) d_offsets[0] = 0;
    #pragma unroll
    for (int i = 0; i < PER; i++) {
        int idx = base + i;
        if (idx < N) {
            d_cursor[idx] = acc;
            acc += cnt[i];
            d_offsets[idx + 1] = acc;
            d_counts[idx] = 0;     // restore zero invariant for next replay
        }
    }
}

__global__ void scatter_kernel(const int* __restrict__ recv, int E) {
    int i = blockIdx.x * blockDim.x + threadIdx.x;
    if (i < E) {
        int pos = atomicAdd(&d_cursor[recv[i]], 1);
        d_sorted[pos] = i;
    }
}

// ---------------------------------------------------------------------------
// Edge accumulation v3: one CTA per node, 256 threads.
// 16-edge chunks double-buffered via cp.async: edge_feats rows (2KB/edge),
// gathered h rows (512B/edge) and attrs (64B/edge) staged in smem; compute is
// smem-only. Thread = (channel c = tid&127, parity par = tid>>7); parity
// splits lm: par0 -> lm0..7 (e0,e1,e2), par1 -> lm8..15 (e2,e3).
// Epilogue writes msg as bf16 hi/lo (identical split the GEMM used to do).
// l_of_lm: [0, 1,1,1, 2,2,2,2,2, 3,3,3,3,3,3,3]
// ---------------------------------------------------------------------------
#define EA_CHUNK 16
// floats: EF 2*16*512 = 16384 | HB 2*16*128 = 4096 | AT 2*16*16 = 512
#define EA_HB_OFF 16384
#define EA_AT_OFF 20480
#define EA_SMEM ((16384 + 4096 + 512) * 4)

__global__ __launch_bounds__(256) void edge_accum_kernel(
    const float* __restrict__ edge_attrs,   // [E,16]
    const float* __restrict__ edge_feats,   // [E,4,128]
    const int*   __restrict__ sender)       // [E]
{
    extern __shared__ float sm[];
    __shared__ int sE[2][EA_CHUNK];
    __shared__ int sS[2][EA_CHUNK];

    int n = blockIdx.x;
    int tid = threadIdx.x;
    int c = tid & 127;
    int par = tid >> 7;

    int beg = d_offsets[n];
    int end = d_offsets[n + 1];
    int nch = (end - beg + EA_CHUNK - 1) / EA_CHUNK;

    uint32_t smb = smem_u32(sm);

    float acc[8];
    #pragma unroll
    for (int i = 0; i < 8; i++) acc[i] = 0.0f;

    if (nch > 0) {
        // prologue: indices + async loads for chunk 0
        {
            int m0 = min(EA_CHUNK, end - beg);
            if (tid < m0) {
                int ee = d_sorted[beg + tid];
                sE[0][tid] = ee;
                sS[0][tid] = sender[ee];
            }
        }
        __syncthreads();
        {
            int m0 = min(EA_CHUNK, end - beg);
            for (int i = tid; i < m0 * 128; i += 256) {
                int j = i >> 7, w = i & 127;
                CP16(smb + (uint32_t)((j * 512 + w * 4) * 4),
                     edge_feats + (size_t)sE[0][j] * 512 + w * 4);
            }
            for (int i = tid; i < m0 * 32; i += 256) {
                int j = i >> 5, w = i & 31;
                CP16(smb + (uint32_t)((EA_HB_OFF + j * 128 + w * 4) * 4),
                     d_h + (size_t)sS[0][j] * 128 + w * 4);
            }
            for (int i = tid; i < m0 * 4; i += 256) {
                int j = i >> 2, w = i & 3;
                CP16(smb + (uint32_t)((EA_AT_OFF + j * 16 + w * 4) * 4),
                     edge_attrs + (size_t)sE[0][j] * 16 + w * 4);
            }
            CP_COMMIT();
        }

        for (int k = 0; k < nch; k++) {
            int buf = k & 1;
            int nb = buf ^ 1;
            bool more = (k + 1 < nch);
            if (more) {
                int mn = min(EA_CHUNK, end - beg - (k + 1) * EA_CHUNK);
                if (tid < mn) {
                    int ee = d_sorted[beg + (k + 1) * EA_CHUNK + tid];
                    sE[nb][tid] = ee;
                    sS[nb][tid] = sender[ee];
                }
            }
            __syncthreads();   // idx ready; prev compute done with buffer nb
            if (more) {
                int mn = min(EA_CHUNK, end - beg - (k + 1) * EA_CHUNK);
                uint32_t eo = smb + (uint32_t)(nb * 8192 * 4);
                for (int i = tid; i < mn * 128; i += 256) {
                    int j = i >> 7, w = i & 127;
                    CP16(eo + (uint32_t)((j * 512 + w * 4) * 4),
                         edge_feats + (size_t)sE[nb][j] * 512 + w * 4);
                }
                uint32_t ho = smb + (uint32_t)((EA_HB_OFF + nb * 2048) * 4);
                for (int i = tid; i < mn * 32; i += 256) {
                    int j = i >> 5, w = i & 31;
                    CP16(ho + (uint32_t)((j * 128 + w * 4) * 4),
                         d_h + (size_t)sS[nb][j] * 128 + w * 4);
                }
                uint32_t ao = smb + (uint32_t)((EA_AT_OFF + nb * 256) * 4);
                for (int i = tid; i < mn * 4; i += 256) {
                    int j = i >> 2, w = i & 3;
                    CP16(ao + (uint32_t)((j * 16 + w * 4) * 4),
                         edge_attrs + (size_t)sE[nb][j] * 16 + w * 4);
                }
                CP_COMMIT();
                cp_wait<1>();   // chunk k complete (k+1 still pending)
            } else {
                cp_wait<0>();
            }
            __syncthreads();   // all threads' copies of chunk k visible

            // compute chunk k (smem only)
            int m = min(EA_CHUNK, end - beg - k * EA_CHUNK);
            const float* ef = sm + buf * 8192;
            const float* hb = sm + EA_HB_OFF + buf * 2048;
            const float* ap = sm + EA_AT_OFF + buf * 256;
            if (par == 0) {
                for (int j = 0; j < m; j++) {
                    float hs = hb[j * 128 + c];
                    const float* a = ap + j * 16;
                    float e0 = ef[j * 512 + c];
                    float e1 = ef[j * 512 + 128 + c];
                    float e2 = ef[j * 512 + 256 + c];
                    float p0 = hs * e0, p1 = hs * e1, p2 = hs * e2;
                    acc[0] += p0 * a[0];
                    acc[1] += p1 * a[1];
                    acc[2] += p1 * a[2];
                    acc[3] += p1 * a[3];
                    acc[4] += p2 * a[4];
                    acc[5] += p2 * a[5];
                    acc[6] += p2 * a[6];
                    acc[7] += p2 * a[7];
                }
            } else {
                for (int j = 0; j < m; j++) {
                    float hs = hb[j * 128 + c];
                    const float* a = ap + j * 16;
                    float e2 = ef[j * 512 + 256 + c];
                    float e3 = ef[j * 512 + 384 + c];
                    float p2 = hs * e2, p3 = hs * e3;
                    acc[0] += p2 * a[8];
                    acc[1] += p3 * a[9];
                    acc[2] += p3 * a[10];
                    acc[3] += p3 * a[11];
                    acc[4] += p3 * a[12];
                    acc[5] += p3 * a[13];
                    acc[6] += p3 * a[14];
                    acc[7] += p3 * a[15];
                }
            }
        }
    }

    // epilogue: write msg as bf16 hi/lo (par owns lm par*8 .. par*8+7)
    size_t ob = ((size_t)n * 16 + par * 8) * 128 + c;
    #pragma unroll
    for (int lm = 0; lm < 8; lm++) {
        float v = acc[lm];
        __nv_bfloat16 hv = __float2bfloat16_rn(v);
        float lv = v - __bfloat162float(hv);
        d_msg_hi[ob + (size_t)lm * 128] = hv;
        d_msg_lo[ob + (size_t)lm * 128] = __float2bfloat16_rn(lv);
    }
}

// ---------------------------------------------------------------------------
// Output GEMM via mma.sync bf16 (HMMA), hi/lo compensated (hh + hl + lh).
// Persistent tile queue. Tile = 128 gathered msg rows x 128 cols x K=128.
// A and B are now PRE-SPLIT bf16 in gmem -> fills are pure cp.async copies.
// Smem: A_hi/A_lo/B_hi/B_lo, each 128 rows x 136 bf16 (padded, ldmatrix
// conflict-free). 8 warps: warp tile 32 rows x 64 cols (2 x m16, 8 x n8).
// B refill skipped when the group repeats (queue is group-ordered).
// ---------------------------------------------------------------------------
#define ROWP 136
#define BUF_BYTES (128 * ROWP * 2)          // 34816
#define DSMEM_BYTES (4 * BUF_BYTES)         // 139264

__global__ __launch_bounds__(256) void out_gemm_mma(float* __restrict__ out, int NE)
{
    extern __shared__ __nv_bfloat16 smb[];
    __nv_bfloat16* A_hi = smb;
    __nv_bfloat16* A_lo = smb + 128 * ROWP;

    __shared__ int s_off[128];
    __shared__ int s_toff[NG_MAX + 1];
    __shared__ int s_eoff[NE_MAX + 1];
    __shared__ int s_tile;

    int tid = threadIdx.x, wid = tid >> 5, lid = tid & 31;
    int NG = NE * 4;
    if (tid <= NG) s_toff[tid] = d_tile_off[tid];
    if (tid <= NE) s_eoff[tid] = d_elem_off[tid];
    __syncthreads();
    int ntiles = s_toff[NG];

    int wm0 = (wid & 3) * 32;     // warp row base
    int wn0 = (wid >> 2) * 64;    // warp col base

    // ldmatrix lane geometry (element offsets within a buffer)
    int a_row0 = wm0 + ((lid >> 3) & 1) * 8 + (lid & 7);
    int a_kadd = ((lid >> 4) & 1) * 8;
    uint32_t aoff[2];
    #pragma unroll
    for (int mt = 0; mt < 2; mt++)
        aoff[mt] = (uint32_t)(((a_row0 + mt * 16) * ROWP + a_kadd) * 2);
    int b_row0 = wn0 + ((lid >> 4) & 1) * 8 + (lid & 7);
    int b_kadd = ((lid >> 3) & 1) * 8;
    uint32_t boff[4];
    #pragma unroll
    for (int p = 0; p < 4; p++)
        boff[p] = (uint32_t)(((b_row0 + p * 16) * ROWP + b_kadd) * 2);

    uint32_t sA_hi = smem_u32(smb);
    uint32_t sA_lo = sA_hi + BUF_BYTES;
    uint32_t sB_hi = sA_hi + 2 * BUF_BYTES;
    uint32_t sB_lo = sA_hi + 3 * BUF_BYTES;

    int g_prev = -1;

    while (true) {
        if (tid == 0) s_tile = atomicAdd(&d_tile_ctr, 1);
        __syncthreads();
        int t = s_tile;
        if (t >= ntiles) break;

        int g = 0;
        while (s_toff[g + 1] <= t) g++;
        int l = g & 3, e = g >> 2;
        int tw = 2 * l + 1;
        int cbeg = s_eoff[e];
        int rows = (s_eoff[e + 1] - cbeg) * tw;
        int tile = (t - s_toff[g]) * 128;
        bool fillB = (g != g_prev);
        g_prev = g;

        if (tid < 128) {
            int rr = tile + tid;
            int off = -1;
            if (rr < rows) {
                int node = d_node_by_elem[cbeg + rr / tw];
                off = (node * 16 + l * l + rr % tw) * 128;
            }
            s_off[tid] = off;
        }
        __syncthreads();

        // --- fill A via cp.async (16 x 16B ops per row, 8 per thread) ---
        #pragma unroll
        for (int q = 0; q < 8; q++) {
            int i = tid + q * 256;
            int r = i >> 4, w = i & 15;
            int off = s_off[r];
            uint32_t d = (uint32_t)((r * ROWP + w * 8) * 2);
            if (off >= 0) {
                CP16(sA_hi + d, d_msg_hi + (size_t)off + w * 8);
                CP16(sA_lo + d, d_msg_lo + (size_t)off + w * 8);
            } else {
                *(uint4*)(A_hi + r * ROWP + w * 8) = make_uint4(0, 0, 0, 0);
                *(uint4*)(A_lo + r * ROWP + w * 8) = make_uint4(0, 0, 0, 0);
            }
        }
        // --- fill B via cp.async only when the group changed ---
        if (fillB) {
            #pragma unroll
            for (int q = 0; q < 8; q++) {
                int i = tid + q * 256;
                int r = i >> 4, w = i & 15;
                uint32_t d = (uint32_t)((r * ROWP + w * 8) * 2);
                CP16(sB_hi + d, d_WcT_hi + ((size_t)g * 128 + r) * 128 + w * 8);
                CP16(sB_lo + d, d_WcT_lo + ((size_t)g * 128 + r) * 128 + w * 8);
            }
        }
        CP_COMMIT();
        cp_wait<0>();
        __syncthreads();

        // --- compute ---
        float acc[2][8][4];
        #pragma unroll
        for (int mt = 0; mt < 2; mt++)
            #pragma unroll
            for (int nt = 0; nt < 8; nt++)
                #pragma unroll
                for (int q = 0; q < 4; q++) acc[mt][nt][q] = 0.0f;

        #pragma unroll
        for (int ks = 0; ks < 8; ks++) {
            uint32_t kb = (uint32_t)(ks * 16 * 2);
            uint32_t ah[2][4], al[2][4];
            #pragma unroll
            for (int mt = 0; mt < 2; mt++) {
                LDSM4(ah[mt][0], ah[mt][1], ah[mt][2], ah[mt][3], sA_hi + aoff[mt] + kb);
                LDSM4(al[mt][0], al[mt][1], al[mt][2], al[mt][3], sA_lo + aoff[mt] + kb);
            }
            uint32_t bh[8][2], bl[8][2];
            #pragma unroll
            for (int p = 0; p < 4; p++) {
                uint32_t r0, r1, r2, r3;
                LDSM4(r0, r1, r2, r3, sB_hi + boff[p] + kb);
                bh[2 * p][0] = r0; bh[2 * p][1] = r1;
                bh[2 * p + 1][0] = r2; bh[2 * p + 1][1] = r3;
                LDSM4(r0, r1, r2, r3, sB_lo + boff[p] + kb);
                bl[2 * p][0] = r0; bl[2 * p][1] = r1;
                bl[2 * p + 1][0] = r2; bl[2 * p + 1][1] = r3;
            }
            #pragma unroll
            for (int mt = 0; mt < 2; mt++)
                #pragma unroll
                for (int nt = 0; nt < 8; nt++) {
                    MMA16816(acc[mt][nt], ah[mt], bh[nt]);   // hi*hi
                    MMA16816(acc[mt][nt], ah[mt], bl[nt]);   // hi*lo
                    MMA16816(acc[mt][nt], al[mt], bh[nt]);   // lo*hi
                }
        }

        // --- epilogue: scatter to out via s_off ---
        #pragma unroll
        for (int mt = 0; mt < 2; mt++) {
            int r0 = wm0 + mt * 16 + (lid >> 2);
            int off0 = s_off[r0];
            int off1 = s_off[r0 + 8];
            #pragma unroll
            for (int nt = 0; nt < 8; nt++) {
                int col = wn0 + nt * 8 + (lid & 3) * 2;
                if (off0 >= 0)
                    *(float2*)&out[(size_t)off0 + col] =
                        make_float2(acc[mt][nt][0], acc[mt][nt][1]);
                if (off1 >= 0)
                    *(float2*)&out[(size_t)off1 + col] =
                        make_float2(acc[mt][nt][2], acc[mt][nt][3]);
            }
        }
        __syncthreads();   // protect smem/s_off/s_tile before next tile
    }
}

// ---------------------------------------------------------------------------
// Launch
// ---------------------------------------------------------------------------
extern "C" void kernel_launch(void* const* d_in, const int* in_sizes, int n_in,
                              void* d_out, int out_size)
{
    const float* node_feats = (const float*)d_in[0];   // [N,128]
    const float* edge_attrs = (const float*)d_in[1];   // [E,16]
    const float* edge_feats = (const float*)d_in[2];   // [E,512]
    const float* W_up       = (const float*)d_in[3];   // [128,128]
    const float* W_lin      = (const float*)d_in[4];   // [4,128,128]
    const float* W_skip     = (const float*)d_in[5];   // [NE,4,128,128]
    const int*   edge_index = (const int*)d_in[6];     // [2,E]
    const int*   node_elem  = (const int*)d_in[7];     // [N]

    int N  = in_sizes[7];
    int E  = in_sizes[1] / 16;
    int NE = in_sizes[5] / (4 * 128 * 128);

    const int* sender = edge_index;
    const int* recv   = edge_index + E;

    int gx = (N + 63) / 64;

    // immediate host-side attribute sets (not stream-ordered; capture-safe)
    cudaFuncSetAttribute(out_gemm_mma,
                         cudaFuncAttributeMaxDynamicSharedMemorySize, DSMEM_BYTES);
    cudaFuncSetAttribute(edge_accum_kernel,
                         cudaFuncAttributeMaxDynamicSharedMemorySize, EA_SMEM);

    // 0. h GEMM + WcT bf16 hi/lo + receiver histogram (counts pre-zeroed:
    //    initial load zeros + scan re-zeroes each replay)
    gemm_fused_kernel<<<dim3(gx, 1, 1 + NE * 4), 256>>>(
        node_feats, W_up, W_lin, W_skip, recv, N, E, NE);
    if (gx < 3)   // degenerate: no helper blocks existed
        hist_kernel<<<(E + 255) / 256, 256>>>(recv, E);

    // 1. scan (+ re-zero counts) + element grouping + tile queue
    scan_elem_kernel<<<2, 1024>>>(node_elem, N, NE);

    // 2. counting-sort scatter
    scatter_kernel<<<(E + 255) / 256, 256>>>(recv, E);

    // 3. per-node edge accumulation -> msg (bf16 hi/lo), cp.async staged
    edge_accum_kernel<<<N, 256, EA_SMEM>>>(edge_attrs, edge_feats, sender);

    // 4. output GEMM on tensor cores (mma.sync bf16, hi/lo compensated)
    out_gemm_mma<<<148, 256, DSMEM_BYTES>>>((float*)d_out, NE);
}

// round 12
// speedup vs baseline: 1.5643x; 1.0226x over previous
#include <cuda_runtime.h>
#include <cuda_bf16.h>
#include <cstdint>

// ---------------------------------------------------------------------------
// MACE invariant message passing:
//   h   = node_feats @ W_up
//   m   = h[sender] * edge_attrs * edge_feats[l_of_lm]   (per edge)
//   msg = segment_sum over receiver  (stored as bf16 hi/lo)
//   out = msg @ ( W_lin[l] @ W_skip[elem,l] / 16 )       (grouped by element)
// Output GEMM: warp-level mma.sync bf16 (HMMA) with hi/lo compensation.
// ---------------------------------------------------------------------------

typedef unsigned long long u64;

#define N_MAX 6144
#define E_MAX 131072
#define NE_MAX 16
#define NG_MAX (NE_MAX * 4)
#define AST 68    // As row stride (floats) in the scalar GEMM (BM=64 + pad)

// Static device scratch (allocation-free per harness rules)
__device__ float d_h[(size_t)N_MAX * 128];
__device__ __nv_bfloat16 d_msg_hi[(size_t)N_MAX * 16 * 128];
__device__ __nv_bfloat16 d_msg_lo[(size_t)N_MAX * 16 * 128];
__device__ __nv_bfloat16 d_WcT_hi[(size_t)NG_MAX * 128 * 128];
__device__ __nv_bfloat16 d_WcT_lo[(size_t)NG_MAX * 128 * 128];
__device__ int   d_sorted[E_MAX];
__device__ int   d_counts[N_MAX];          // zero-init; scan re-zeroes after use
__device__ int   d_offsets[N_MAX + 1];
__device__ int   d_cursor[N_MAX];
__device__ int   d_node_by_elem[N_MAX];
__device__ int   d_elem_off[NE_MAX + 1];
__device__ int   d_elem_cur[NE_MAX];
__device__ int   d_tile_off[NG_MAX + 1];
__device__ int   d_tile_ctr;

// --------------------------- helpers ---------------------------------------
__device__ __forceinline__ uint32_t smem_u32(const void* p) {
    uint32_t a;
    asm("{ .reg .u64 t; cvta.to.shared.u64 t, %1; cvt.u32.u64 %0, t; }"
        : "=r"(a) : "l"(p));
    return a;
}

#define CP16(dst, src) \
    asm volatile("cp.async.cg.shared.global [%0], [%1], 16;" \
        :: "r"(dst), "l"(src) : "memory")
#define CP_COMMIT() asm volatile("cp.async.commit_group;" ::: "memory")
template <int W>
__device__ __forceinline__ void cp_wait() {
    asm volatile("cp.async.wait_group %0;" :: "n"(W) : "memory");
}

#define LDSM4(r0, r1, r2, r3, addr) \
    asm volatile("ldmatrix.sync.aligned.m8n8.x4.shared.b16 {%0,%1,%2,%3}, [%4];" \
        : "=r"(r0), "=r"(r1), "=r"(r2), "=r"(r3) : "r"(addr))

#define MMA16816(c, a, b) \
    asm volatile("mma.sync.aligned.m16n8k16.row.col.f32.bf16.bf16.f32 " \
        "{%0,%1,%2,%3}, {%4,%5,%6,%7}, {%8,%9}, {%0,%1,%2,%3};" \
        : "+f"((c)[0]), "+f"((c)[1]), "+f"((c)[2]), "+f"((c)[3]) \
        : "r"((a)[0]), "r"((a)[1]), "r"((a)[2]), "r"((a)[3]), \
          "r"((b)[0]), "r"((b)[1]))

// ---------------------------------------------------------------------------
// Fused GEMM kernel (scalar fp32, BM=64, BN=128, BK=16, acc 4x8 -> no spills):
//   z == 0          : h = node_feats @ W_up          (tiles over blockIdx.x)
//   z >= 1, x <= 1  : WcT[g] rows x*64..+63 = transpose(W_lin[l] @ W_skip[g]/16)
//   z >= 1, x >= 2  : helper blocks run the receiver histogram
// ---------------------------------------------------------------------------
__global__ __launch_bounds__(256) void gemm_fused_kernel(
    const float* __restrict__ node_feats,
    const float* __restrict__ W_up,
    const float* __restrict__ W_lin,
    const float* __restrict__ W_skip,
    const int*   __restrict__ recv,
    int N, int E, int NE)
{
    const float* A;
    const float* B;
    int M;
    float scale;
    int z = blockIdx.z;
    int g = z - 1;
    int row0;

    if (z == 0) {
        A = node_feats; B = W_up; M = N; scale = 1.0f;
        row0 = blockIdx.x * 64;
    } else {
        if (blockIdx.x >= 2) {
            int nb  = gridDim.x - 2;
            int id  = (z - 1) * nb + (blockIdx.x - 2);
            int tot = (int)(gridDim.z - 1) * nb;
            for (int i = id * 256 + threadIdx.x; i < E; i += tot * 256)
                atomicAdd(&d_counts[recv[i]], 1);
            return;
        }
        int l = g & 3;
        A = W_lin  + (size_t)l * 16384;
        B = W_skip + (size_t)g * 16384;
        M = 128; scale = 1.0f / 16.0f;
        row0 = blockIdx.x * 64;
    }

    __shared__ float As[16 * AST];
    __shared__ float Bs[16 * 128];

    int tid = threadIdx.x;
    int ty = tid >> 4;      // 0..15 -> 4-row group
    int tx = tid & 15;      // 0..15 -> 4-col group (x2 halves)

    float acc[4][8];
    #pragma unroll
    for (int i = 0; i < 4; i++)
        #pragma unroll
        for (int j = 0; j < 8; j++) acc[i][j] = 0.0f;

    for (int kc = 0; kc < 128; kc += 16) {
        #pragma unroll
        for (int i = 0; i < 4; i++) {
            int idx = tid + i * 256;
            int r = idx >> 4, kk = idx & 15;
            int row = row0 + r;
            As[kk * AST + r] = (row < M) ? A[(size_t)row * 128 + kc + kk] : 0.0f;
        }
        #pragma unroll
        for (int i = 0; i < 8; i++) {
            int idx = tid + i * 256;
            int kk = idx >> 7, d = idx & 127;
            Bs[kk * 128 + d] = B[(size_t)(kc + kk) * 128 + d];
        }
        __syncthreads();
        #pragma unroll
        for (int kk = 0; kk < 16; kk++) {
            float4 a0 = *(const float4*)&As[kk * AST + ty * 4];
            float4 b0 = *(const float4*)&Bs[kk * 128 + tx * 4];
            float4 b1 = *(const float4*)&Bs[kk * 128 + 64 + tx * 4];
            float av[4] = {a0.x, a0.y, a0.z, a0.w};
            float bv[8] = {b0.x, b0.y, b0.z, b0.w, b1.x, b1.y, b1.z, b1.w};
            #pragma unroll
            for (int i = 0; i < 4; i++)
                #pragma unroll
                for (int j = 0; j < 8; j++) acc[i][j] += av[i] * bv[j];
        }
        __syncthreads();
    }

    if (z == 0) {
        #pragma unroll
        for (int i = 0; i < 4; i++) {
            int row = row0 + ty * 4 + i;
            if (row < M) {
                *(float4*)&d_h[(size_t)row * 128 + tx * 4] =
                    make_float4(acc[i][0], acc[i][1], acc[i][2], acc[i][3]);
                *(float4*)&d_h[(size_t)row * 128 + 64 + tx * 4] =
                    make_float4(acc[i][4], acc[i][5], acc[i][6], acc[i][7]);
            }
        }
    } else {
        // transposed bf16 hi/lo write: WcT[g][d][c], c = Wc row, d = Wc col
        #pragma unroll
        for (int i = 0; i < 4; i++) {
            int c = row0 + ty * 4 + i;
            #pragma unroll
            for (int j = 0; j < 8; j++) {
                int d = (j < 4) ? (tx * 4 + j) : (64 + tx * 4 + (j - 4));
                float v = acc[i][j] * scale;
                __nv_bfloat16 hv = __float2bfloat16_rn(v);
                float lv = v - __bfloat162float(hv);
                size_t o = ((size_t)g * 128 + d) * 128 + c;
                d_WcT_hi[o] = hv;
                d_WcT_lo[o] = __float2bfloat16_rn(lv);
            }
        }
    }
}

// Fallback hist (only if the fused grid had no helper blocks)
__global__ void hist_kernel(const int* __restrict__ recv, int E) {
    int i = blockIdx.x * blockDim.x + threadIdx.x;
    if (i < E) atomicAdd(&d_counts[recv[i]], 1);
}

// ---------------------------------------------------------------------------
// block 0: warp-shuffle scan of d_counts -> d_offsets / d_cursor, then
//          RE-ZEROES d_counts (keeps the zero invariant across graph replays)
// block 1: group nodes by element; tile prefix; reset tile counter
// ---------------------------------------------------------------------------
__global__ void scan_elem_kernel(const int* __restrict__ node_elem, int N, int NE) {
    int tid = threadIdx.x;

    if (blockIdx.x == 1) {
        __shared__ int scnt[NE_MAX];
        if (tid < NE) scnt[tid] = 0;
        __syncthreads();
        for (int i = tid; i < N; i += blockDim.x) atomicAdd(&scnt[node_elem[i]], 1);
        __syncthreads();
        if (tid == 0) {
            int run = 0;
            for (int e = 0; e < NE; e++) { d_elem_off[e] = run; d_elem_cur[e] = run; run += scnt[e]; }
            d_elem_off[NE] = run;
            int tp = 0;
            for (int g = 0; g < NE * 4; g++) {
                int l = g & 3;
                int rows = scnt[g >> 2] * (2 * l + 1);
                d_tile_off[g] = tp;
                tp += (rows + 127) >> 7;
            }
            d_tile_off[NE * 4] = tp;
            d_tile_ctr = 0;
        }
        __syncthreads();
        for (int i = tid; i < N; i += blockDim.x) {
            int pos = atomicAdd(&d_elem_cur[node_elem[i]], 1);
            d_node_by_elem[pos] = i;
        }
        return;
    }

    // block 0: scan (1024 threads x 6 elems = 6144 >= N_MAX)
    __shared__ int wtot[32];
    const int PER = 6;
    int lane = tid & 31, w = tid >> 5;
    int base = tid * PER;
    int cnt[PER];
    int run = 0;
    #pragma unroll
    for (int i = 0; i < PER; i++) {
        cnt[i] = (base + i < N) ? d_counts[base + i] : 0;
        run += cnt[i];
    }
    int ws = run;
    #pragma unroll
    for (int o = 1; o < 32; o <<= 1) {
        int t = __shfl_up_sync(0xffffffffu, ws, o);
        if (lane >= o) ws += t;
    }
    if (lane == 31) wtot[w] = ws;
    __syncthreads();
    if (w == 0) {
        int v = wtot[lane];
        #pragma unroll
        for (int o = 1; o < 32; o <<= 1) {
            int t = __shfl_up_sync(0xffffffffu, v, o);
            if (lane >= o) v += t;
        }
        wtot[lane] = v;
    }
    __syncthreads();
    int acc = (w ? wtot[w - 1] : 0) + (ws - run);
    if (tid == 0) d_offsets[0] = 0;
    #pragma unroll
    for (int i = 0; i < PER; i++) {
        int idx = base + i;
        if (idx < N) {
            d_cursor[idx] = acc;
            acc += cnt[i];
            d_offsets[idx + 1] = acc;
            d_counts[idx] = 0;     // restore zero invariant for next replay
        }
    }
}

__global__ void scatter_kernel(const int* __restrict__ recv, int E) {
    int i = blockIdx.x * blockDim.x + threadIdx.x;
    if (i < E) {
        int pos = atomicAdd(&d_cursor[recv[i]], 1);
        d_sorted[pos] = i;
    }
}

// ---------------------------------------------------------------------------
// Edge accumulation v4b: one CTA per node, 256 threads.
// 8-edge chunks, 3 smem buffers (ef 48KB + attrs 1.5KB -> 4 CTAs/SM), issue
// for chunk k+2 overlaps compute of chunk k (prefetch distance 16 edges).
// ef copy: thread (cj=tid>>5, cw=tid&31) issues 4 CP16s covering the FULL
// 512-float row (cw*4 + {0,128,256,384}).  [R10 bug: only 1 CP16 -> 1/4 row]
// h via direct LDG (L2-resident, reg-pipelined); senders staged 2 chunks
// ahead. Thread = (channel c = tid&127, parity par = tid>>7); par0 lm0..7,
// par1 lm8..15. Epilogue writes msg as bf16 hi/lo.
// l_of_lm: [0, 1,1,1, 2,2,2,2,2, 3,3,3,3,3,3,3]
// ---------------------------------------------------------------------------
#define EA_CHUNK 8
#define EA_EF_FL (EA_CHUNK * 512)          // 4096 floats per buffer
#define EA_AT_OFF (3 * EA_EF_FL)           // 12288
#define EA_AT_FL (EA_CHUNK * 16)           // 128 floats per buffer
#define EA_SMEM ((3 * EA_EF_FL + 3 * EA_AT_FL) * 4)   // 50688 bytes

__global__ __launch_bounds__(256) void edge_accum_kernel(
    const float* __restrict__ edge_attrs,   // [E,16]
    const float* __restrict__ edge_feats,   // [E,4,128]
    const int*   __restrict__ sender)       // [E]
{
    extern __shared__ float sm[];
    __shared__ int sS[3][EA_CHUNK];

    int n = blockIdx.x;
    int tid = threadIdx.x;
    int c = tid & 127;
    int par = tid >> 7;

    int beg = d_offsets[n];
    int nedge = d_offsets[n + 1] - beg;
    int nch = (nedge + EA_CHUNK - 1) / EA_CHUNK;

    uint32_t smb = smem_u32(sm);

    float acc[8];
    #pragma unroll
    for (int i = 0; i < 8; i++) acc[i] = 0.0f;

    // copy-job geometry: ef: edge cj = tid>>5, float4 lane cw = tid&31,
    //                    each thread covers cw*4 + {0,128,256,384} (full row)
    int cj = tid >> 5, cw = tid & 31;
    int aj = tid >> 2, aw = tid & 3;       // attrs: edge aj, float4 aw (tid<32)

    // issue loads for chunk kk into buffer kk%3 (no sync required)
    auto issue = [&](int kk) {
        int m = min(EA_CHUNK, nedge - kk * EA_CHUNK);
        int b = kk % 3;
        if (cj < m) {
            int ee = d_sorted[beg + kk * EA_CHUNK + cj];
            const float* src = edge_feats + (size_t)ee * 512;
            uint32_t dst = smb + (uint32_t)((b * EA_EF_FL + cj * 512) * 4);
            #pragma unroll
            for (int q = 0; q < 4; q++)
                CP16(dst + (uint32_t)((cw * 4 + q * 128) * 4),
                     src + cw * 4 + q * 128);
            if (cw == 0) sS[b][cj] = sender[ee];
        }
        if (tid < 32 && aj < m) {
            int ee = d_sorted[beg + kk * EA_CHUNK + aj];
            CP16(smb + (uint32_t)((EA_AT_OFF + b * EA_AT_FL + aj * 16 + aw * 4) * 4),
                 edge_attrs + (size_t)ee * 16 + aw * 4);
        }
    };

    if (nch > 0) {
        if (0 < nch) issue(0);
        CP_COMMIT();
        if (1 < nch) issue(1);
        CP_COMMIT();

        for (int k = 0; k < nch; k++) {
            if (k + 2 < nch) issue(k + 2);
            CP_COMMIT();             // empty group ok; keeps count uniform
            cp_wait<2>();            // chunk k complete
            __syncthreads();         // copies + senders visible to all

            int m = min(EA_CHUNK, nedge - k * EA_CHUNK);
            int b = k % 3;
            const float* ef = sm + b * EA_EF_FL;
            const float* ap = sm + EA_AT_OFF + b * EA_AT_FL;

            float hs = d_h[(size_t)sS[b][0] * 128 + c];
            for (int j = 0; j < m; j++) {
                float hn = (j + 1 < m) ? d_h[(size_t)sS[b][j + 1] * 128 + c] : 0.0f;
                const float* a = ap + j * 16;
                if (par == 0) {
                    float e0 = ef[j * 512 + c];
                    float e1 = ef[j * 512 + 128 + c];
                    float e2 = ef[j * 512 + 256 + c];
                    float p0 = hs * e0, p1 = hs * e1, p2 = hs * e2;
                    acc[0] += p0 * a[0];
                    acc[1] += p1 * a[1];
                    acc[2] += p1 * a[2];
                    acc[3] += p1 * a[3];
                    acc[4] += p2 * a[4];
                    acc[5] += p2 * a[5];
                    acc[6] += p2 * a[6];
                    acc[7] += p2 * a[7];
                } else {
                    float e2 = ef[j * 512 + 256 + c];
                    float e3 = ef[j * 512 + 384 + c];
                    float p2 = hs * e2, p3 = hs * e3;
                    acc[0] += p2 * a[8];
                    acc[1] += p3 * a[9];
                    acc[2] += p3 * a[10];
                    acc[3] += p3 * a[11];
                    acc[4] += p3 * a[12];
                    acc[5] += p3 * a[13];
                    acc[6] += p3 * a[14];
                    acc[7] += p3 * a[15];
                }
                hs = hn;
            }
            __syncthreads();         // release buffer b for issue(k+3)
        }
    }

    // epilogue: write msg as bf16 hi/lo (par owns lm par*8 .. par*8+7)
    size_t ob = ((size_t)n * 16 + par * 8) * 128 + c;
    #pragma unroll
    for (int lm = 0; lm < 8; lm++) {
        float v = acc[lm];
        __nv_bfloat16 hv = __float2bfloat16_rn(v);
        float lv = v - __bfloat162float(hv);
        d_msg_hi[ob + (size_t)lm * 128] = hv;
        d_msg_lo[ob + (size_t)lm * 128] = __float2bfloat16_rn(lv);
    }
}

// ---------------------------------------------------------------------------
// Output GEMM via mma.sync bf16 (HMMA), hi/lo compensated (hh + hl + lh).
// Persistent tile queue. Tile = 128 gathered msg rows x 128 cols x K=128.
// A and B are PRE-SPLIT bf16 in gmem -> fills are pure cp.async copies.
// Smem: A_hi/A_lo/B_hi/B_lo, each 128 rows x 136 bf16 (padded, ldmatrix
// conflict-free). 8 warps: warp tile 32 rows x 64 cols (2 x m16, 8 x n8).
// B refill skipped when the group repeats (queue is group-ordered).
// ---------------------------------------------------------------------------
#define ROWP 136
#define BUF_BYTES (128 * ROWP * 2)          // 34816
#define DSMEM_BYTES (4 * BUF_BYTES)         // 139264

__global__ __launch_bounds__(256) void out_gemm_mma(float* __restrict__ out, int NE)
{
    extern __shared__ __nv_bfloat16 smb[];
    __nv_bfloat16* A_hi = smb;
    __nv_bfloat16* A_lo = smb + 128 * ROWP;

    __shared__ int s_off[128];
    __shared__ int s_toff[NG_MAX + 1];
    __shared__ int s_eoff[NE_MAX + 1];
    __shared__ int s_tile;

    int tid = threadIdx.x, wid = tid >> 5, lid = tid & 31;
    int NG = NE * 4;
    if (tid <= NG) s_toff[tid] = d_tile_off[tid];
    if (tid <= NE) s_eoff[tid] = d_elem_off[tid];
    __syncthreads();
    int ntiles = s_toff[NG];

    int wm0 = (wid & 3) * 32;     // warp row base
    int wn0 = (wid >> 2) * 64;    // warp col base

    // ldmatrix lane geometry (element offsets within a buffer)
    int a_row0 = wm0 + ((lid >> 3) & 1) * 8 + (lid & 7);
    int a_kadd = ((lid >> 4) & 1) * 8;
    uint32_t aoff[2];
    #pragma unroll
    for (int mt = 0; mt < 2; mt++)
        aoff[mt] = (uint32_t)(((a_row0 + mt * 16) * ROWP + a_kadd) * 2);
    int b_row0 = wn0 + ((lid >> 4) & 1) * 8 + (lid & 7);
    int b_kadd = ((lid >> 3) & 1) * 8;
    uint32_t boff[4];
    #pragma unroll
    for (int p = 0; p < 4; p++)
        boff[p] = (uint32_t)(((b_row0 + p * 16) * ROWP + b_kadd) * 2);

    uint32_t sA_hi = smem_u32(smb);
    uint32_t sA_lo = sA_hi + BUF_BYTES;
    uint32_t sB_hi = sA_hi + 2 * BUF_BYTES;
    uint32_t sB_lo = sA_hi + 3 * BUF_BYTES;

    int g_prev = -1;

    while (true) {
        if (tid == 0) s_tile = atomicAdd(&d_tile_ctr, 1);
        __syncthreads();
        int t = s_tile;
        if (t >= ntiles) break;

        int g = 0;
        while (s_toff[g + 1] <= t) g++;
        int l = g & 3, e = g >> 2;
        int tw = 2 * l + 1;
        int cbeg = s_eoff[e];
        int rows = (s_eoff[e + 1] - cbeg) * tw;
        int tile = (t - s_toff[g]) * 128;
        bool fillB = (g != g_prev);
        g_prev = g;

        if (tid < 128) {
            int rr = tile + tid;
            int off = -1;
            if (rr < rows) {
                int node = d_node_by_elem[cbeg + rr / tw];
                off = (node * 16 + l * l + rr % tw) * 128;
            }
            s_off[tid] = off;
        }
        __syncthreads();

        // --- fill A via cp.async (16 x 16B ops per row, 8 per thread) ---
        #pragma unroll
        for (int q = 0; q < 8; q++) {
            int i = tid + q * 256;
            int r = i >> 4, w = i & 15;
            int off = s_off[r];
            uint32_t d = (uint32_t)((r * ROWP + w * 8) * 2);
            if (off >= 0) {
                CP16(sA_hi + d, d_msg_hi + (size_t)off + w * 8);
                CP16(sA_lo + d, d_msg_lo + (size_t)off + w * 8);
            } else {
                *(uint4*)(A_hi + r * ROWP + w * 8) = make_uint4(0, 0, 0, 0);
                *(uint4*)(A_lo + r * ROWP + w * 8) = make_uint4(0, 0, 0, 0);
            }
        }
        // --- fill B via cp.async only when the group changed ---
        if (fillB) {
            #pragma unroll
            for (int q = 0; q < 8; q++) {
                int i = tid + q * 256;
                int r = i >> 4, w = i & 15;
                uint32_t d = (uint32_t)((r * ROWP + w * 8) * 2);
                CP16(sB_hi + d, d_WcT_hi + ((size_t)g * 128 + r) * 128 + w * 8);
                CP16(sB_lo + d, d_WcT_lo + ((size_t)g * 128 + r) * 128 + w * 8);
            }
        }
        CP_COMMIT();
        cp_wait<0>();
        __syncthreads();

        // --- compute ---
        float acc[2][8][4];
        #pragma unroll
        for (int mt = 0; mt < 2; mt++)
            #pragma unroll
            for (int nt = 0; nt < 8; nt++)
                #pragma unroll
                for (int q = 0; q < 4; q++) acc[mt][nt][q] = 0.0f;

        #pragma unroll
        for (int ks = 0; ks < 8; ks++) {
            uint32_t kb = (uint32_t)(ks * 16 * 2);
            uint32_t ah[2][4], al[2][4];
            #pragma unroll
            for (int mt = 0; mt < 2; mt++) {
                LDSM4(ah[mt][0], ah[mt][1], ah[mt][2], ah[mt][3], sA_hi + aoff[mt] + kb);
                LDSM4(al[mt][0], al[mt][1], al[mt][2], al[mt][3], sA_lo + aoff[mt] + kb);
            }
            uint32_t bh[8][2], bl[8][2];
            #pragma unroll
            for (int p = 0; p < 4; p++) {
                uint32_t r0, r1, r2, r3;
                LDSM4(r0, r1, r2, r3, sB_hi + boff[p] + kb);
                bh[2 * p][0] = r0; bh[2 * p][1] = r1;
                bh[2 * p + 1][0] = r2; bh[2 * p + 1][1] = r3;
                LDSM4(r0, r1, r2, r3, sB_lo + boff[p] + kb);
                bl[2 * p][0] = r0; bl[2 * p][1] = r1;
                bl[2 * p + 1][0] = r2; bl[2 * p + 1][1] = r3;
            }
            #pragma unroll
            for (int mt = 0; mt < 2; mt++)
                #pragma unroll
                for (int nt = 0; nt < 8; nt++) {
                    MMA16816(acc[mt][nt], ah[mt], bh[nt]);   // hi*hi
                    MMA16816(acc[mt][nt], ah[mt], bl[nt]);   // hi*lo
                    MMA16816(acc[mt][nt], al[mt], bh[nt]);   // lo*hi
                }
        }

        // --- epilogue: scatter to out via s_off ---
        #pragma unroll
        for (int mt = 0; mt < 2; mt++) {
            int r0 = wm0 + mt * 16 + (lid >> 2);
            int off0 = s_off[r0];
            int off1 = s_off[r0 + 8];
            #pragma unroll
            for (int nt = 0; nt < 8; nt++) {
                int col = wn0 + nt * 8 + (lid & 3) * 2;
                if (off0 >= 0)
                    *(float2*)&out[(size_t)off0 + col] =
                        make_float2(acc[mt][nt][0], acc[mt][nt][1]);
                if (off1 >= 0)
                    *(float2*)&out[(size_t)off1 + col] =
                        make_float2(acc[mt][nt][2], acc[mt][nt][3]);
            }
        }
        __syncthreads();   // protect smem/s_off/s_tile before next tile
    }
}

// ---------------------------------------------------------------------------
// Launch
// ---------------------------------------------------------------------------
extern "C" void kernel_launch(void* const* d_in, const int* in_sizes, int n_in,
                              void* d_out, int out_size)
{
    const float* node_feats = (const float*)d_in[0];   // [N,128]
    const float* edge_attrs = (const float*)d_in[1];   // [E,16]
    const float* edge_feats = (const float*)d_in[2];   // [E,512]
    const float* W_up       = (const float*)d_in[3];   // [128,128]
    const float* W_lin      = (const float*)d_in[4];   // [4,128,128]
    const float* W_skip     = (const float*)d_in[5];   // [NE,4,128,128]
    const int*   edge_index = (const int*)d_in[6];     // [2,E]
    const int*   node_elem  = (const int*)d_in[7];     // [N]

    int N  = in_sizes[7];
    int E  = in_sizes[1] / 16;
    int NE = in_sizes[5] / (4 * 128 * 128);

    const int* sender = edge_index;
    const int* recv   = edge_index + E;

    int gx = (N + 63) / 64;

    // immediate host-side attribute sets (not stream-ordered; capture-safe)
    cudaFuncSetAttribute(out_gemm_mma,
                         cudaFuncAttributeMaxDynamicSharedMemorySize, DSMEM_BYTES);
    cudaFuncSetAttribute(edge_accum_kernel,
                         cudaFuncAttributeMaxDynamicSharedMemorySize, EA_SMEM);

    // 0. h GEMM + WcT bf16 hi/lo + receiver histogram (counts pre-zeroed:
    //    initial load zeros + scan re-zeroes each replay)
    gemm_fused_kernel<<<dim3(gx, 1, 1 + NE * 4), 256>>>(
        node_feats, W_up, W_lin, W_skip, recv, N, E, NE);
    if (gx < 3)   // degenerate: no helper blocks existed
        hist_kernel<<<(E + 255) / 256, 256>>>(recv, E);

    // 1. scan (+ re-zero counts) + element grouping + tile queue
    scan_elem_kernel<<<2, 1024>>>(node_elem, N, NE);

    // 2. counting-sort scatter
    scatter_kernel<<<(E + 255) / 256, 256>>>(recv, E);

    // 3. per-node edge accumulation -> msg (bf16 hi/lo), depth-3 cp.async
    edge_accum_kernel<<<N, 256, EA_SMEM>>>(edge_attrs, edge_feats, sender);

    // 4. output GEMM on tensor cores (mma.sync bf16, hi/lo compensated)
    out_gemm_mma<<<148, 256, DSMEM_BYTES>>>((float*)d_out, NE);
}

// round 13
// speedup vs baseline: 1.7337x; 1.1083x over previous
#include <cuda_runtime.h>
#include <cuda_bf16.h>
#include <cstdint>

// ---------------------------------------------------------------------------
// MACE invariant message passing:
//   h   = node_feats @ W_up
//   m   = h[sender] * edge_attrs * edge_feats[l_of_lm]   (per edge)
//   msg = segment_sum over receiver  (stored as bf16 hi/lo)
//   out = msg @ ( W_lin[l] @ W_skip[elem,l] / 16 )       (grouped by element)
// Output GEMM: warp-level mma.sync bf16 (HMMA) with hi/lo compensation.
// ---------------------------------------------------------------------------

typedef unsigned long long u64;

#define N_MAX 6144
#define E_MAX 131072
#define NE_MAX 16
#define NG_MAX (NE_MAX * 4)
#define AST 68    // As row stride (floats) in the scalar GEMM (BM=64 + pad)

// Static device scratch (allocation-free per harness rules)
__device__ float d_h[(size_t)N_MAX * 128];
__device__ __nv_bfloat16 d_msg_hi[(size_t)N_MAX * 16 * 128];
__device__ __nv_bfloat16 d_msg_lo[(size_t)N_MAX * 16 * 128];
__device__ __nv_bfloat16 d_WcT_hi[(size_t)NG_MAX * 128 * 128];
__device__ __nv_bfloat16 d_WcT_lo[(size_t)NG_MAX * 128 * 128];
__device__ int   d_sorted[E_MAX];
__device__ int   d_counts[N_MAX];          // zero-init; scan re-zeroes after use
__device__ int   d_offsets[N_MAX + 1];
__device__ int   d_cursor[N_MAX];
__device__ int   d_node_by_elem[N_MAX];
__device__ int   d_elem_off[NE_MAX + 1];
__device__ int   d_elem_cur[NE_MAX];
__device__ int   d_tile_off[NG_MAX + 1];
__device__ int   d_tile_ctr;

// --------------------------- helpers ---------------------------------------
__device__ __forceinline__ uint32_t smem_u32(const void* p) {
    uint32_t a;
    asm("{ .reg .u64 t; cvta.to.shared.u64 t, %1; cvt.u32.u64 %0, t; }"
        : "=r"(a) : "l"(p));
    return a;
}

#define CP16(dst, src) \
    asm volatile("cp.async.cg.shared.global [%0], [%1], 16;" \
        :: "r"(dst), "l"(src) : "memory")
#define CP_COMMIT() asm volatile("cp.async.commit_group;" ::: "memory")
template <int W>
__device__ __forceinline__ void cp_wait() {
    asm volatile("cp.async.wait_group %0;" :: "n"(W) : "memory");
}

#define LDSM4(r0, r1, r2, r3, addr) \
    asm volatile("ldmatrix.sync.aligned.m8n8.x4.shared.b16 {%0,%1,%2,%3}, [%4];" \
        : "=r"(r0), "=r"(r1), "=r"(r2), "=r"(r3) : "r"(addr))

#define MMA16816(c, a, b) \
    asm volatile("mma.sync.aligned.m16n8k16.row.col.f32.bf16.bf16.f32 " \
        "{%0,%1,%2,%3}, {%4,%5,%6,%7}, {%8,%9}, {%0,%1,%2,%3};" \
        : "+f"((c)[0]), "+f"((c)[1]), "+f"((c)[2]), "+f"((c)[3]) \
        : "r"((a)[0]), "r"((a)[1]), "r"((a)[2]), "r"((a)[3]), \
          "r"((b)[0]), "r"((b)[1]))

// ---------------------------------------------------------------------------
// Fused GEMM kernel (scalar fp32, BM=64, BN=128, BK=16, acc 4x8 -> no spills):
//   z == 0          : h = node_feats @ W_up          (tiles over blockIdx.x)
//   z >= 1, x <= 1  : WcT[g] rows x*64..+63 = transpose(W_lin[l] @ W_skip[g]/16)
//   z >= 1, x >= 2  : helper blocks run the receiver histogram
// ---------------------------------------------------------------------------
__global__ __launch_bounds__(256) void gemm_fused_kernel(
    const float* __restrict__ node_feats,
    const float* __restrict__ W_up,
    const float* __restrict__ W_lin,
    const float* __restrict__ W_skip,
    const int*   __restrict__ recv,
    int N, int E, int NE)
{
    const float* A;
    const float* B;
    int M;
    float scale;
    int z = blockIdx.z;
    int g = z - 1;
    int row0;

    if (z == 0) {
        A = node_feats; B = W_up; M = N; scale = 1.0f;
        row0 = blockIdx.x * 64;
    } else {
        if (blockIdx.x >= 2) {
            int nb  = gridDim.x - 2;
            int id  = (z - 1) * nb + (blockIdx.x - 2);
            int tot = (int)(gridDim.z - 1) * nb;
            for (int i = id * 256 + threadIdx.x; i < E; i += tot * 256)
                atomicAdd(&d_counts[recv[i]], 1);
            return;
        }
        int l = g & 3;
        A = W_lin  + (size_t)l * 16384;
        B = W_skip + (size_t)g * 16384;
        M = 128; scale = 1.0f / 16.0f;
        row0 = blockIdx.x * 64;
    }

    __shared__ float As[16 * AST];
    __shared__ float Bs[16 * 128];

    int tid = threadIdx.x;
    int ty = tid >> 4;      // 0..15 -> 4-row group
    int tx = tid & 15;      // 0..15 -> 4-col group (x2 halves)

    float acc[4][8];
    #pragma unroll
    for (int i = 0; i < 4; i++)
        #pragma unroll
        for (int j = 0; j < 8; j++) acc[i][j] = 0.0f;

    for (int kc = 0; kc < 128; kc += 16) {
        #pragma unroll
        for (int i = 0; i < 4; i++) {
            int idx = tid + i * 256;
            int r = idx >> 4, kk = idx & 15;
            int row = row0 + r;
            As[kk * AST + r] = (row < M) ? A[(size_t)row * 128 + kc + kk] : 0.0f;
        }
        #pragma unroll
        for (int i = 0; i < 8; i++) {
            int idx = tid + i * 256;
            int kk = idx >> 7, d = idx & 127;
            Bs[kk * 128 + d] = B[(size_t)(kc + kk) * 128 + d];
        }
        __syncthreads();
        #pragma unroll
        for (int kk = 0; kk < 16; kk++) {
            float4 a0 = *(const float4*)&As[kk * AST + ty * 4];
            float4 b0 = *(const float4*)&Bs[kk * 128 + tx * 4];
            float4 b1 = *(const float4*)&Bs[kk * 128 + 64 + tx * 4];
            float av[4] = {a0.x, a0.y, a0.z, a0.w};
            float bv[8] = {b0.x, b0.y, b0.z, b0.w, b1.x, b1.y, b1.z, b1.w};
            #pragma unroll
            for (int i = 0; i < 4; i++)
                #pragma unroll
                for (int j = 0; j < 8; j++) acc[i][j] += av[i] * bv[j];
        }
        __syncthreads();
    }

    if (z == 0) {
        #pragma unroll
        for (int i = 0; i < 4; i++) {
            int row = row0 + ty * 4 + i;
            if (row < M) {
                *(float4*)&d_h[(size_t)row * 128 + tx * 4] =
                    make_float4(acc[i][0], acc[i][1], acc[i][2], acc[i][3]);
                *(float4*)&d_h[(size_t)row * 128 + 64 + tx * 4] =
                    make_float4(acc[i][4], acc[i][5], acc[i][6], acc[i][7]);
            }
        }
    } else {
        // transposed bf16 hi/lo write: WcT[g][d][c], c = Wc row, d = Wc col
        #pragma unroll
        for (int i = 0; i < 4; i++) {
            int c = row0 + ty * 4 + i;
            #pragma unroll
            for (int j = 0; j < 8; j++) {
                int d = (j < 4) ? (tx * 4 + j) : (64 + tx * 4 + (j - 4));
                float v = acc[i][j] * scale;
                __nv_bfloat16 hv = __float2bfloat16_rn(v);
                float lv = v - __bfloat162float(hv);
                size_t o = ((size_t)g * 128 + d) * 128 + c;
                d_WcT_hi[o] = hv;
                d_WcT_lo[o] = __float2bfloat16_rn(lv);
            }
        }
    }
}

// Fallback hist (only if the fused grid had no helper blocks)
__global__ void hist_kernel(const int* __restrict__ recv, int E) {
    int i = blockIdx.x * blockDim.x + threadIdx.x;
    if (i < E) atomicAdd(&d_counts[recv[i]], 1);
}

// ---------------------------------------------------------------------------
// block 0: warp-shuffle scan of d_counts -> d_offsets / d_cursor, then
//          RE-ZEROES d_counts (keeps the zero invariant across graph replays)
// block 1: group nodes by element; tile prefix (64-row tiles); reset counter
// ---------------------------------------------------------------------------
__global__ void scan_elem_kernel(const int* __restrict__ node_elem, int N, int NE) {
    int tid = threadIdx.x;

    if (blockIdx.x == 1) {
        __shared__ int scnt[NE_MAX];
        if (tid < NE) scnt[tid] = 0;
        __syncthreads();
        for (int i = tid; i < N; i += blockDim.x) atomicAdd(&scnt[node_elem[i]], 1);
        __syncthreads();
        if (tid == 0) {
            int run = 0;
            for (int e = 0; e < NE; e++) { d_elem_off[e] = run; d_elem_cur[e] = run; run += scnt[e]; }
            d_elem_off[NE] = run;
            int tp = 0;
            for (int g = 0; g < NE * 4; g++) {
                int l = g & 3;
                int rows = scnt[g >> 2] * (2 * l + 1);
                d_tile_off[g] = tp;
                tp += (rows + 63) >> 6;     // 64-row tiles
            }
            d_tile_off[NE * 4] = tp;
            d_tile_ctr = 0;
        }
        __syncthreads();
        for (int i = tid; i < N; i += blockDim.x) {
            int pos = atomicAdd(&d_elem_cur[node_elem[i]], 1);
            d_node_by_elem[pos] = i;
        }
        return;
    }

    // block 0: scan (1024 threads x 6 elems = 6144 >= N_MAX)
    __shared__ int wtot[32];
    const int PER = 6;
    int lane = tid & 31, w = tid >> 5;
    int base = tid * PER;
    int cnt[PER];
    int run = 0;
    #pragma unroll
    for (int i = 0; i < PER; i++) {
        cnt[i] = (base + i < N) ? d_counts[base + i] : 0;
        run += cnt[i];
    }
    int ws = run;
    #pragma unroll
    for (int o = 1; o < 32; o <<= 1) {
        int t = __shfl_up_sync(0xffffffffu, ws, o);
        if (lane >= o) ws += t;
    }
    if (lane == 31) wtot[w] = ws;
    __syncthreads();
    if (w == 0) {
        int v = wtot[lane];
        #pragma unroll
        for (int o = 1; o < 32; o <<= 1) {
            int t = __shfl_up_sync(0xffffffffu, v, o);
            if (lane >= o) v += t;
        }
        wtot[lane] = v;
    }
    __syncthreads();
    int acc = (w ? wtot[w - 1] : 0) + (ws - run);
    if (tid == 0) d_offsets[0] = 0;
    #pragma unroll
    for (int i = 0; i < PER; i++) {
        int idx = base + i;
        if (idx < N) {
            d_cursor[idx] = acc;
            acc += cnt[i];
            d_offsets[idx + 1] = acc;
            d_counts[idx] = 0;     // restore zero invariant for next replay
        }
    }
}

__global__ void scatter_kernel(const int* __restrict__ recv, int E) {
    int i = blockIdx.x * blockDim.x + threadIdx.x;
    if (i < E) {
        int pos = atomicAdd(&d_cursor[recv[i]], 1);
        d_sorted[pos] = i;
    }
}

// ---------------------------------------------------------------------------
// Edge accumulation (R8 structure, measured best): one CTA per node, 256
// threads. Thread = (channel c = tid&127, parity par = tid>>7), 16 lm accs
// per thread. Parities process alternating edges with depth-2 register
// pipeline (10 LDGs in flight), combined via smem. Streaming hints on
// read-once edge data. Epilogue writes msg as bf16 hi/lo.
// l_of_lm: [0, 1,1,1, 2,2,2,2,2, 3,3,3,3,3,3,3]
// ---------------------------------------------------------------------------
__global__ __launch_bounds__(256) void edge_accum_kernel(
    const float* __restrict__ edge_attrs,   // [E,16]
    const float* __restrict__ edge_feats,   // [E,4,128]
    const int*   __restrict__ sender)       // [E]
{
    int n = blockIdx.x;
    int tid = threadIdx.x;
    int c = tid & 127;
    int par = tid >> 7;

    __shared__ float s_attr[32][16];
    __shared__ int   s_e[32];
    __shared__ int   s_send[32];
    __shared__ float s_part[16][128];

    float acc[16];
    #pragma unroll
    for (int i = 0; i < 16; i++) acc[i] = 0.0f;

    int beg = d_offsets[n];
    int end = d_offsets[n + 1];

    for (int base = beg; base < end; base += 32) {
        int m = end - base;
        if (m > 32) m = 32;
        if (tid < m) {
            int ee = d_sorted[base + tid];
            s_e[tid] = ee;
            s_send[tid] = sender[ee];
        }
        for (int i = tid; i < m * 16; i += 256) {
            int j = i >> 4;
            s_attr[j][i & 15] = __ldcs(&edge_attrs[(size_t)d_sorted[base + j] * 16 + (i & 15)]);
        }
        __syncthreads();

        // depth-2 software pipeline over this parity's edges (stride 2)
        int j = par;
        float A0[5] = {0.f, 0.f, 0.f, 0.f, 0.f};
        float A1[5] = {0.f, 0.f, 0.f, 0.f, 0.f};
        if (j < m) {
            const float* efp = edge_feats + (size_t)s_e[j] * 512;
            A0[0] = __ldcs(efp + c);       A0[1] = __ldcs(efp + 128 + c);
            A0[2] = __ldcs(efp + 256 + c); A0[3] = __ldcs(efp + 384 + c);
            A0[4] = d_h[(size_t)s_send[j] * 128 + c];
        }
        if (j + 2 < m) {
            const float* efp = edge_feats + (size_t)s_e[j + 2] * 512;
            A1[0] = __ldcs(efp + c);       A1[1] = __ldcs(efp + 128 + c);
            A1[2] = __ldcs(efp + 256 + c); A1[3] = __ldcs(efp + 384 + c);
            A1[4] = d_h[(size_t)s_send[j + 2] * 128 + c];
        }
        while (j < m) {
            float A2[5] = {0.f, 0.f, 0.f, 0.f, 0.f};
            if (j + 4 < m) {
                const float* efp = edge_feats + (size_t)s_e[j + 4] * 512;
                A2[0] = __ldcs(efp + c);       A2[1] = __ldcs(efp + 128 + c);
                A2[2] = __ldcs(efp + 256 + c); A2[3] = __ldcs(efp + 384 + c);
                A2[4] = d_h[(size_t)s_send[j + 4] * 128 + c];
            }
            const float* at = s_attr[j];
            float hs = A0[4];
            float p0 = hs * A0[0], p1 = hs * A0[1], p2 = hs * A0[2], p3 = hs * A0[3];
            acc[0]  += p0 * at[0];
            acc[1]  += p1 * at[1];
            acc[2]  += p1 * at[2];
            acc[3]  += p1 * at[3];
            acc[4]  += p2 * at[4];
            acc[5]  += p2 * at[5];
            acc[6]  += p2 * at[6];
            acc[7]  += p2 * at[7];
            acc[8]  += p2 * at[8];
            acc[9]  += p3 * at[9];
            acc[10] += p3 * at[10];
            acc[11] += p3 * at[11];
            acc[12] += p3 * at[12];
            acc[13] += p3 * at[13];
            acc[14] += p3 * at[14];
            acc[15] += p3 * at[15];
            #pragma unroll
            for (int q = 0; q < 5; q++) { A0[q] = A1[q]; A1[q] = A2[q]; }
            j += 2;
        }
        __syncthreads();
    }

    if (par) {
        #pragma unroll
        for (int lm = 0; lm < 16; lm++) s_part[lm][c] = acc[lm];
    }
    __syncthreads();
    if (!par) {
        size_t ob = (size_t)n * 2048 + c;
        #pragma unroll
        for (int lm = 0; lm < 16; lm++) {
            float v = acc[lm] + s_part[lm][c];
            __nv_bfloat16 hv = __float2bfloat16_rn(v);
            float lv = v - __bfloat162float(hv);
            d_msg_hi[ob + (size_t)lm * 128] = hv;
            d_msg_lo[ob + (size_t)lm * 128] = __float2bfloat16_rn(lv);
        }
    }
}

// ---------------------------------------------------------------------------
// Output GEMM via mma.sync bf16 (HMMA), hi/lo compensated (hh + hl + lh).
// Persistent tile queue, BM=64 tiles -> 102KB smem -> 2 CTAs/SM for overlap.
// Tile = 64 gathered msg rows x 128 cols x K=128. A/B pre-split bf16 in gmem;
// fills are pure cp.async. Smem rows padded to 136 bf16 (ldmatrix
// conflict-free). 8 warps: warp tile 32 rows x 32 cols (2 x m16, 4 x n8).
// B refill skipped when the group repeats (queue is group-ordered).
// ---------------------------------------------------------------------------
#define ROWP 136
#define A_BUF (64 * ROWP * 2)               // 17408
#define B_BUF (128 * ROWP * 2)              // 34816
#define DSMEM_BYTES (2 * A_BUF + 2 * B_BUF) // 104448

__global__ __launch_bounds__(256, 2) void out_gemm_mma(float* __restrict__ out, int NE)
{
    extern __shared__ __nv_bfloat16 smb[];
    __nv_bfloat16* A_hi = smb;
    __nv_bfloat16* A_lo = smb + 64 * ROWP;

    __shared__ int s_off[64];
    __shared__ int s_toff[NG_MAX + 1];
    __shared__ int s_eoff[NE_MAX + 1];
    __shared__ int s_tile;

    int tid = threadIdx.x, wid = tid >> 5, lid = tid & 31;
    int NG = NE * 4;
    if (tid <= NG) s_toff[tid] = d_tile_off[tid];
    if (tid <= NE) s_eoff[tid] = d_elem_off[tid];
    __syncthreads();
    int ntiles = s_toff[NG];

    int wm0 = (wid & 1) * 32;     // warp row base (0/32)
    int wn0 = (wid >> 1) * 32;    // warp col base (0..96)

    // ldmatrix lane geometry (byte offsets within a buffer)
    int a_row0 = wm0 + ((lid >> 3) & 1) * 8 + (lid & 7);
    int a_kadd = ((lid >> 4) & 1) * 8;
    uint32_t aoff[2];
    #pragma unroll
    for (int mt = 0; mt < 2; mt++)
        aoff[mt] = (uint32_t)(((a_row0 + mt * 16) * ROWP + a_kadd) * 2);
    int b_row0 = wn0 + ((lid >> 4) & 1) * 8 + (lid & 7);
    int b_kadd = ((lid >> 3) & 1) * 8;
    uint32_t boff[2];
    #pragma unroll
    for (int p = 0; p < 2; p++)
        boff[p] = (uint32_t)(((b_row0 + p * 16) * ROWP + b_kadd) * 2);

    uint32_t sA_hi = smem_u32(smb);
    uint32_t sA_lo = sA_hi + A_BUF;
    uint32_t sB_hi = sA_hi + 2 * A_BUF;
    uint32_t sB_lo = sA_hi + 2 * A_BUF + B_BUF;

    int g_prev = -1;

    while (true) {
        if (tid == 0) s_tile = atomicAdd(&d_tile_ctr, 1);
        __syncthreads();
        int t = s_tile;
        if (t >= ntiles) break;

        int g = 0;
        while (s_toff[g + 1] <= t) g++;
        int l = g & 3, e = g >> 2;
        int tw = 2 * l + 1;
        int cbeg = s_eoff[e];
        int rows = (s_eoff[e + 1] - cbeg) * tw;
        int tile = (t - s_toff[g]) * 64;
        bool fillB = (g != g_prev);
        g_prev = g;

        if (tid < 64) {
            int rr = tile + tid;
            int off = -1;
            if (rr < rows) {
                int node = d_node_by_elem[cbeg + rr / tw];
                off = (node * 16 + l * l + rr % tw) * 128;
            }
            s_off[tid] = off;
        }
        __syncthreads();

        // --- fill A via cp.async (64 rows x 16 float4 jobs, 4 per thread) ---
        #pragma unroll
        for (int q = 0; q < 4; q++) {
            int i = tid + q * 256;
            int r = i >> 4, w = i & 15;
            int off = s_off[r];
            uint32_t d = (uint32_t)((r * ROWP + w * 8) * 2);
            if (off >= 0) {
                CP16(sA_hi + d, d_msg_hi + (size_t)off + w * 8);
                CP16(sA_lo + d, d_msg_lo + (size_t)off + w * 8);
            } else {
                *(uint4*)(A_hi + r * ROWP + w * 8) = make_uint4(0, 0, 0, 0);
                *(uint4*)(A_lo + r * ROWP + w * 8) = make_uint4(0, 0, 0, 0);
            }
        }
        // --- fill B via cp.async only when the group changed ---
        if (fillB) {
            #pragma unroll
            for (int q = 0; q < 8; q++) {
                int i = tid + q * 256;
                int r = i >> 4, w = i & 15;
                uint32_t d = (uint32_t)((r * ROWP + w * 8) * 2);
                CP16(sB_hi + d, d_WcT_hi + ((size_t)g * 128 + r) * 128 + w * 8);
                CP16(sB_lo + d, d_WcT_lo + ((size_t)g * 128 + r) * 128 + w * 8);
            }
        }
        CP_COMMIT();
        cp_wait<0>();
        __syncthreads();

        // --- compute ---
        float acc[2][4][4];
        #pragma unroll
        for (int mt = 0; mt < 2; mt++)
            #pragma unroll
            for (int nt = 0; nt < 4; nt++)
                #pragma unroll
                for (int q = 0; q < 4; q++) acc[mt][nt][q] = 0.0f;

        #pragma unroll
        for (int ks = 0; ks < 8; ks++) {
            uint32_t kb = (uint32_t)(ks * 16 * 2);
            uint32_t ah[2][4], al[2][4];
            #pragma unroll
            for (int mt = 0; mt < 2; mt++) {
                LDSM4(ah[mt][0], ah[mt][1], ah[mt][2], ah[mt][3], sA_hi + aoff[mt] + kb);
                LDSM4(al[mt][0], al[mt][1], al[mt][2], al[mt][3], sA_lo + aoff[mt] + kb);
            }
            uint32_t bh[4][2], bl[4][2];
            #pragma unroll
            for (int p = 0; p < 2; p++) {
                uint32_t r0, r1, r2, r3;
                LDSM4(r0, r1, r2, r3, sB_hi + boff[p] + kb);
                bh[2 * p][0] = r0; bh[2 * p][1] = r1;
                bh[2 * p + 1][0] = r2; bh[2 * p + 1][1] = r3;
                LDSM4(r0, r1, r2, r3, sB_lo + boff[p] + kb);
                bl[2 * p][0] = r0; bl[2 * p][1] = r1;
                bl[2 * p + 1][0] = r2; bl[2 * p + 1][1] = r3;
            }
            #pragma unroll
            for (int mt = 0; mt < 2; mt++)
                #pragma unroll
                for (int nt = 0; nt < 4; nt++) {
                    MMA16816(acc[mt][nt], ah[mt], bh[nt]);   // hi*hi
                    MMA16816(acc[mt][nt], ah[mt], bl[nt]);   // hi*lo
                    MMA16816(acc[mt][nt], al[mt], bh[nt]);   // lo*hi
                }
        }

        // --- epilogue: scatter to out via s_off ---
        #pragma unroll
        for (int mt = 0; mt < 2; mt++) {
            int r0 = wm0 + mt * 16 + (lid >> 2);
            int off0 = s_off[r0];
            int off1 = s_off[r0 + 8];
            #pragma unroll
            for (int nt = 0; nt < 4; nt++) {
                int col = wn0 + nt * 8 + (lid & 3) * 2;
                if (off0 >= 0)
                    *(float2*)&out[(size_t)off0 + col] =
                        make_float2(acc[mt][nt][0], acc[mt][nt][1]);
                if (off1 >= 0)
                    *(float2*)&out[(size_t)off1 + col] =
                        make_float2(acc[mt][nt][2], acc[mt][nt][3]);
            }
        }
        __syncthreads();   // protect smem/s_off/s_tile before next tile
    }
}

// ---------------------------------------------------------------------------
// Launch
// ---------------------------------------------------------------------------
extern "C" void kernel_launch(void* const* d_in, const int* in_sizes, int n_in,
                              void* d_out, int out_size)
{
    const float* node_feats = (const float*)d_in[0];   // [N,128]
    const float* edge_attrs = (const float*)d_in[1];   // [E,16]
    const float* edge_feats = (const float*)d_in[2];   // [E,512]
    const float* W_up       = (const float*)d_in[3];   // [128,128]
    const float* W_lin      = (const float*)d_in[4];   // [4,128,128]
    const float* W_skip     = (const float*)d_in[5];   // [NE,4,128,128]
    const int*   edge_index = (const int*)d_in[6];     // [2,E]
    const int*   node_elem  = (const int*)d_in[7];     // [N]

    int N  = in_sizes[7];
    int E  = in_sizes[1] / 16;
    int NE = in_sizes[5] / (4 * 128 * 128);

    const int* sender = edge_index;
    const int* recv   = edge_index + E;

    int gx = (N + 63) / 64;

    // immediate host-side attribute set (not stream-ordered; capture-safe)
    cudaFuncSetAttribute(out_gemm_mma,
                         cudaFuncAttributeMaxDynamicSharedMemorySize, DSMEM_BYTES);

    // 0. h GEMM + WcT bf16 hi/lo + receiver histogram (counts pre-zeroed:
    //    initial load zeros + scan re-zeroes each replay)
    gemm_fused_kernel<<<dim3(gx, 1, 1 + NE * 4), 256>>>(
        node_feats, W_up, W_lin, W_skip, recv, N, E, NE);
    if (gx < 3)   // degenerate: no helper blocks existed
        hist_kernel<<<(E + 255) / 256, 256>>>(recv, E);

    // 1. scan (+ re-zero counts) + element grouping + tile queue (64-row)
    scan_elem_kernel<<<2, 1024>>>(node_elem, N, NE);

    // 2. counting-sort scatter
    scatter_kernel<<<(E + 255) / 256, 256>>>(recv, E);

    // 3. per-node edge accumulation -> msg (bf16 hi/lo), R8 structure
    edge_accum_kernel<<<N, 256>>>(edge_attrs, edge_feats, sender);

    // 4. output GEMM on tensor cores (mma.sync bf16, hi/lo compensated)
    out_gemm_mma<<<296, 256, DSMEM_BYTES>>>((float*)d_out, NE);
}